// round 1
// baseline (speedup 1.0000x reference)
#include <cuda_runtime.h>
#include <math.h>

#define EMB 512
#define NHEAD 8
#define DHEAD 64
#define SEQ 4096
#define BATCH 2
#define WINDOW 128
#define MTOT (BATCH * SEQ)   // 8192

// scratch: 0=Q, 1=K, 2=V, 3=attn_out  (each [MTOT, EMB] fp32)
__device__ float g_scr[4][(size_t)MTOT * EMB];

// ---------------------------------------------------------------------------
// C[m,n] = sum_k A[m,k] * W[n,k] + bias[n]   (K = N = EMB = 512)
// BM=128, BN=128, BK=16, 256 threads, 8x8 per thread
// ---------------------------------------------------------------------------
#define GBM 128
#define GBN 128
#define GBK 16

__global__ __launch_bounds__(256) void gemm_bias_kernel(
    const float* __restrict__ Ain, int a_sel,
    const float* __restrict__ W, const float* __restrict__ bias,
    float* __restrict__ Cout, int c_sel)
{
    const float* A = (a_sel >= 0) ? g_scr[a_sel] : Ain;
    float* C = (c_sel >= 0) ? g_scr[c_sel] : Cout;

    __shared__ float As[GBK][GBM];
    __shared__ float Bs[GBK][GBN];

    const int tid = threadIdx.x;
    const int bm = blockIdx.x * GBM;
    const int bn = blockIdx.y * GBN;
    const int ty = tid >> 4;       // 0..15  -> M dir (8 rows each)
    const int tx = tid & 15;       // 0..15  -> N dir (8 cols each)

    float acc[8][8];
#pragma unroll
    for (int i = 0; i < 8; i++)
#pragma unroll
        for (int j = 0; j < 8; j++) acc[i][j] = 0.f;

    for (int k0 = 0; k0 < EMB; k0 += GBK) {
        // A tile: 128 rows x 16 cols = 512 float4, 2 per thread
#pragma unroll
        for (int l = 0; l < 2; l++) {
            int idx = tid + l * 256;      // float4 index
            int row = idx >> 2;           // 0..127
            int c4  = idx & 3;            // 0..3
            float4 v = *(const float4*)&A[(size_t)(bm + row) * EMB + k0 + c4 * 4];
            As[c4 * 4 + 0][row] = v.x;
            As[c4 * 4 + 1][row] = v.y;
            As[c4 * 4 + 2][row] = v.z;
            As[c4 * 4 + 3][row] = v.w;
        }
        // B tile: W rows bn..bn+127, cols k0..k0+15
#pragma unroll
        for (int l = 0; l < 2; l++) {
            int idx = tid + l * 256;
            int row = idx >> 2;
            int c4  = idx & 3;
            float4 v = *(const float4*)&W[(size_t)(bn + row) * EMB + k0 + c4 * 4];
            Bs[c4 * 4 + 0][row] = v.x;
            Bs[c4 * 4 + 1][row] = v.y;
            Bs[c4 * 4 + 2][row] = v.z;
            Bs[c4 * 4 + 3][row] = v.w;
        }
        __syncthreads();

#pragma unroll
        for (int kk = 0; kk < GBK; kk++) {
            float4 a0 = *(const float4*)&As[kk][ty * 8];
            float4 a1 = *(const float4*)&As[kk][ty * 8 + 4];
            float4 b0 = *(const float4*)&Bs[kk][tx * 8];
            float4 b1 = *(const float4*)&Bs[kk][tx * 8 + 4];
            float a[8] = {a0.x, a0.y, a0.z, a0.w, a1.x, a1.y, a1.z, a1.w};
            float b[8] = {b0.x, b0.y, b0.z, b0.w, b1.x, b1.y, b1.z, b1.w};
#pragma unroll
            for (int i = 0; i < 8; i++)
#pragma unroll
                for (int j = 0; j < 8; j++)
                    acc[i][j] += a[i] * b[j];
        }
        __syncthreads();
    }

#pragma unroll
    for (int i = 0; i < 8; i++) {
        int m = bm + ty * 8 + i;
#pragma unroll
        for (int j = 0; j < 8; j += 4) {
            int n = bn + tx * 8 + j;
            float4 o;
            o.x = acc[i][j + 0] + bias[n + 0];
            o.y = acc[i][j + 1] + bias[n + 1];
            o.z = acc[i][j + 2] + bias[n + 2];
            o.w = acc[i][j + 3] + bias[n + 3];
            *(float4*)&C[(size_t)m * EMB + n] = o;
        }
    }
}

// ---------------------------------------------------------------------------
// Banded flash attention. One block per (batch, head, 64-query tile).
// smem: Qs[d][q] 64x64 | Ks[d][k] 64x64 | Vs[k][d] 64x64 | Ps[k][q] 64x64
//       + scale_s[64] + l_s[64]
// ---------------------------------------------------------------------------
#define ATTN_SMEM_BYTES ((4 * 4096 + 128) * 4)

__global__ __launch_bounds__(256) void attn_kernel()
{
    extern __shared__ float sm[];
    float* Qs = sm;                 // [64][64]  (d-major)
    float* Ks = sm + 4096;          // [64][64]  (d-major)
    float* Vs = sm + 8192;          // [64][64]  (key-major)
    float* Ps = sm + 12288;         // [64][64]  (key-major)
    float* scale_s = sm + 16384;    // [64]
    float* l_s = sm + 16448;        // [64]

    const int tid = threadIdx.x;
    const int qb = blockIdx.x;
    const int h = blockIdx.y;
    const int b = blockIdx.z;
    const int q0 = qb * 64;
    const int ty = tid >> 4;        // 0..15 -> query dir (4 each)
    const int tx = tid & 15;        // 0..15 -> key/dim dir (4 each)

    const float* Q = g_scr[0];
    const float* K = g_scr[1];
    const float* V = g_scr[2];
    const size_t base = (size_t)b * SEQ * EMB + (size_t)h * DHEAD;

    // load Q tile transposed into Qs[d][q]
#pragma unroll
    for (int l = 0; l < 4; l++) {
        int idx = tid + l * 256;      // float4 index, 16 per row
        int row = idx >> 4;           // query 0..63
        int c4  = idx & 15;           // 0..15
        float4 v = *(const float4*)&Q[base + (size_t)(q0 + row) * EMB + c4 * 4];
        Qs[(c4 * 4 + 0) * 64 + row] = v.x;
        Qs[(c4 * 4 + 1) * 64 + row] = v.y;
        Qs[(c4 * 4 + 2) * 64 + row] = v.z;
        Qs[(c4 * 4 + 3) * 64 + row] = v.w;
    }

    float m_run = -1e30f, l_run = 0.f;
    float acc[4][4];
#pragma unroll
    for (int i = 0; i < 4; i++)
#pragma unroll
        for (int j = 0; j < 4; j++) acc[i][j] = 0.f;

    const float rs = 0.044194173824159216f;  // 1/sqrt(512)

    int lo = q0 - WINDOW; if (lo < 0) lo = 0;
    int hi = q0 + 64 + WINDOW; if (hi > SEQ) hi = SEQ;

    __syncthreads();

    for (int kc = lo; kc < hi; kc += 64) {
        // load K chunk (transposed) and V chunk (direct)
#pragma unroll
        for (int l = 0; l < 4; l++) {
            int idx = tid + l * 256;
            int row = idx >> 4;       // key 0..63
            int c4  = idx & 15;
            float4 kv = *(const float4*)&K[base + (size_t)(kc + row) * EMB + c4 * 4];
            Ks[(c4 * 4 + 0) * 64 + row] = kv.x;
            Ks[(c4 * 4 + 1) * 64 + row] = kv.y;
            Ks[(c4 * 4 + 2) * 64 + row] = kv.z;
            Ks[(c4 * 4 + 3) * 64 + row] = kv.w;
            float4 vv = *(const float4*)&V[base + (size_t)(kc + row) * EMB + c4 * 4];
            *(float4*)&Vs[row * 64 + c4 * 4] = vv;
        }
        __syncthreads();

        // scores: q = ty*4+i, key = tx*4+j
        float s[4][4];
#pragma unroll
        for (int i = 0; i < 4; i++)
#pragma unroll
            for (int j = 0; j < 4; j++) s[i][j] = 0.f;

#pragma unroll 8
        for (int d = 0; d < 64; d++) {
            float4 a4 = *(const float4*)&Qs[d * 64 + ty * 4];
            float4 b4 = *(const float4*)&Ks[d * 64 + tx * 4];
            float a[4] = {a4.x, a4.y, a4.z, a4.w};
            float bb[4] = {b4.x, b4.y, b4.z, b4.w};
#pragma unroll
            for (int i = 0; i < 4; i++)
#pragma unroll
                for (int j = 0; j < 4; j++)
                    s[i][j] += a[i] * bb[j];
        }

        // mask + scale, write Ps[key][q]
#pragma unroll
        for (int i = 0; i < 4; i++) {
            int qg = q0 + ty * 4 + i;
#pragma unroll
            for (int j = 0; j < 4; j++) {
                int kg = kc + tx * 4 + j;
                int dd = qg - kg; if (dd < 0) dd = -dd;
                float val = (dd <= WINDOW) ? s[i][j] * rs : -1e30f;
                Ps[(tx * 4 + j) * 64 + (ty * 4 + i)] = val;
            }
        }
        __syncthreads();

        // online softmax update (one thread per query)
        if (tid < 64) {
            int q = tid;
            float mo = m_run;
            float mx = mo;
            for (int k2 = 0; k2 < 64; k2++) mx = fmaxf(mx, Ps[k2 * 64 + q]);
            float fac = __expf(mo - mx);
            float l2 = l_run * fac;
            for (int k2 = 0; k2 < 64; k2++) {
                float p = __expf(Ps[k2 * 64 + q] - mx);
                Ps[k2 * 64 + q] = p;
                l2 += p;
            }
            m_run = mx;
            l_run = l2;
            scale_s[q] = fac;
            l_s[q] = l2;
        }
        __syncthreads();

        // rescale accumulators and accumulate P @ V
#pragma unroll
        for (int i = 0; i < 4; i++) {
            float f = scale_s[ty * 4 + i];
#pragma unroll
            for (int j = 0; j < 4; j++) acc[i][j] *= f;
        }
#pragma unroll 8
        for (int k2 = 0; k2 < 64; k2++) {
            float4 a4 = *(const float4*)&Ps[k2 * 64 + ty * 4];
            float4 v4 = *(const float4*)&Vs[k2 * 64 + tx * 4];
            float a[4] = {a4.x, a4.y, a4.z, a4.w};
            float vv[4] = {v4.x, v4.y, v4.z, v4.w};
#pragma unroll
            for (int i = 0; i < 4; i++)
#pragma unroll
                for (int j = 0; j < 4; j++)
                    acc[i][j] += a[i] * vv[j];
        }
        __syncthreads();
    }

    // normalize and write attn output to g_scr[3] in [token, emb] layout
#pragma unroll
    for (int i = 0; i < 4; i++) {
        int qg = q0 + ty * 4 + i;
        float inv = 1.f / l_s[ty * 4 + i];
        float4 o;
        o.x = acc[i][0] * inv;
        o.y = acc[i][1] * inv;
        o.z = acc[i][2] * inv;
        o.w = acc[i][3] * inv;
        *(float4*)&g_scr[3][(size_t)(b * SEQ + qg) * EMB + h * DHEAD + tx * 4] = o;
    }
}

// ---------------------------------------------------------------------------
extern "C" void kernel_launch(void* const* d_in, const int* in_sizes, int n_in,
                              void* d_out, int out_size)
{
    const float* x  = (const float*)d_in[0];
    const float* Wq = (const float*)d_in[1];
    const float* bq = (const float*)d_in[2];
    const float* Wk = (const float*)d_in[3];
    const float* bk = (const float*)d_in[4];
    const float* Wv = (const float*)d_in[5];
    const float* bv = (const float*)d_in[6];
    const float* Wo = (const float*)d_in[7];
    const float* bo = (const float*)d_in[8];
    float* out = (float*)d_out;

    dim3 gg(MTOT / GBM, EMB / GBN);

    gemm_bias_kernel<<<gg, 256>>>(x, -1, Wq, bq, nullptr, 0);
    gemm_bias_kernel<<<gg, 256>>>(x, -1, Wk, bk, nullptr, 1);
    gemm_bias_kernel<<<gg, 256>>>(x, -1, Wv, bv, nullptr, 2);

    cudaFuncSetAttribute(attn_kernel, cudaFuncAttributeMaxDynamicSharedMemorySize,
                         ATTN_SMEM_BYTES);
    attn_kernel<<<dim3(SEQ / 64, NHEAD, BATCH), 256, ATTN_SMEM_BYTES>>>();

    gemm_bias_kernel<<<gg, 256>>>(nullptr, 3, Wo, bo, out, -1);
}

// round 4
// speedup vs baseline: 1.5648x; 1.5648x over previous
#include <cuda_runtime.h>
#include <cuda_bf16.h>
#include <math.h>
#include <stdint.h>

#define EMB 512
#define NHEAD 8
#define DHEAD 64
#define SEQ 4096
#define BATCH 2
#define WINDOW 128
#define MTOT (BATCH * SEQ)   // 8192

// scratch: 0=Q, 1=K, 2=V, 3=attn_out  (each [MTOT, EMB] fp32)
__device__ float g_scr[4][(size_t)MTOT * EMB];
// bf16 split operands
__device__ __nv_bfloat16 g_xhi[(size_t)MTOT * EMB];
__device__ __nv_bfloat16 g_xlo[(size_t)MTOT * EMB];
__device__ __nv_bfloat16 g_ahi[(size_t)MTOT * EMB];
__device__ __nv_bfloat16 g_alo[(size_t)MTOT * EMB];
__device__ __nv_bfloat16 g_whi[4][EMB * EMB];
__device__ __nv_bfloat16 g_wlo[4][EMB * EMB];

// ---------------------------------------------------------------------------
// helpers (base sm_103 ISA only: cp.async + ldmatrix + mma.sync)
// ---------------------------------------------------------------------------
static __device__ __forceinline__ uint32_t smem_u32(const void* p) {
    uint32_t a;
    asm("{ .reg .u64 t; cvta.to.shared.u64 t, %1; cvt.u32.u64 %0, t; }"
        : "=r"(a) : "l"(p));
    return a;
}
static __device__ __forceinline__ void cp16(uint32_t dst, const void* src) {
    asm volatile("cp.async.cg.shared.global [%0], [%1], 16;" :: "r"(dst), "l"(src));
}
#define CP_COMMIT() asm volatile("cp.async.commit_group;" ::: "memory")
#define CP_WAIT(n)  asm volatile("cp.async.wait_group %0;" :: "n"(n) : "memory")

static __device__ __forceinline__ void ldm_x4(uint32_t& r0, uint32_t& r1,
                                              uint32_t& r2, uint32_t& r3, uint32_t a) {
    asm volatile("ldmatrix.sync.aligned.m8n8.x4.shared.b16 {%0,%1,%2,%3}, [%4];"
                 : "=r"(r0), "=r"(r1), "=r"(r2), "=r"(r3) : "r"(a));
}
static __device__ __forceinline__ void mma_bf16(float* d, const uint32_t* a, const uint32_t* b) {
    asm volatile(
        "mma.sync.aligned.m16n8k16.row.col.f32.bf16.bf16.f32 "
        "{%0,%1,%2,%3}, {%4,%5,%6,%7}, {%8,%9}, {%0,%1,%2,%3};"
        : "+f"(d[0]), "+f"(d[1]), "+f"(d[2]), "+f"(d[3])
        : "r"(a[0]), "r"(a[1]), "r"(a[2]), "r"(a[3]), "r"(b[0]), "r"(b[1]));
}

// ---------------------------------------------------------------------------
// fp32 -> bf16 hi/lo split.  src_sel >= 0 -> read g_scr[src_sel]
// dst_sel: 0 -> x, 1 -> attn_out, 2..5 -> W[dst_sel-2]
// ---------------------------------------------------------------------------
__global__ __launch_bounds__(256) void conv_split(
    const float* __restrict__ srcp, int src_sel, int dst_sel, int n4)
{
    int i = blockIdx.x * blockDim.x + threadIdx.x;
    if (i >= n4) return;
    const float* src = (src_sel >= 0) ? g_scr[src_sel] : srcp;
    __nv_bfloat16 *hi, *lo;
    if (dst_sel == 0)      { hi = g_xhi; lo = g_xlo; }
    else if (dst_sel == 1) { hi = g_ahi; lo = g_alo; }
    else                   { hi = g_whi[dst_sel - 2]; lo = g_wlo[dst_sel - 2]; }

    float4 v = ((const float4*)src)[i];
    float f[4] = {v.x, v.y, v.z, v.w};
    __align__(8) __nv_bfloat16 h[4], l[4];
#pragma unroll
    for (int j = 0; j < 4; j++) {
        h[j] = __float2bfloat16(f[j]);
        l[j] = __float2bfloat16(f[j] - __bfloat162float(h[j]));
    }
    ((uint2*)hi)[i] = *(uint2*)h;
    ((uint2*)lo)[i] = *(uint2*)l;
}

// ---------------------------------------------------------------------------
// HMMA GEMM: C[m,n] = sum_k A[m,k]*W[n,k] + bias[n],  M=8192, N=K=512
// A = Ahi+Alo, W = Whi+Wlo (bf16 hi/lo split; 3 MMA passes, fp32 accum).
// CTA tile 128x128, K-chunk 64, cp.async double buffer, 8 warps (2Mx4N).
// smem tile layout: [128 rows][64 bf16] (128B rows), chunk swizzle c^=(r&7).
// ---------------------------------------------------------------------------
#define TILE_BYTES 16384            // 128 * 128B
#define STAGE_BYTES (4 * TILE_BYTES)
#define GEMM_SMEM (2 * STAGE_BYTES)

// stage loader as a real function: k0 is a parameter, no macro capture.
static __device__ __forceinline__ void load_stage(
    uint32_t sbase, int buf, int k0, int tid,
    const __nv_bfloat16* t0, const __nv_bfloat16* t1,
    const __nv_bfloat16* t2, const __nv_bfloat16* t3)
{
    const __nv_bfloat16* tsrc[4] = {t0, t1, t2, t3};
    uint32_t stb = sbase + (uint32_t)buf * STAGE_BYTES;
#pragma unroll
    for (int i = 0; i < 16; i++) {
        int t = i >> 2;
        int idx = tid + i * 256;
        int rr = (idx >> 3) & 127;
        int cc = idx & 7;
        uint32_t dst = stb + t * TILE_BYTES + rr * 128 + ((cc ^ (rr & 7)) * 16);
        cp16(dst, tsrc[t] + (size_t)rr * EMB + k0 + cc * 8);
    }
    CP_COMMIT();
}

__global__ __launch_bounds__(256, 1) void gemm_mma(
    const float* __restrict__ bias, float* __restrict__ Cext,
    int a_sel, int w_idx, int c_sel)
{
    extern __shared__ __align__(1024) char dsm[];
    const uint32_t sbase = smem_u32(dsm);

    const __nv_bfloat16* Ah = a_sel ? g_ahi : g_xhi;
    const __nv_bfloat16* Al = a_sel ? g_alo : g_xlo;
    const __nv_bfloat16* Bh = g_whi[w_idx];
    const __nv_bfloat16* Bl = g_wlo[w_idx];
    float* C = (c_sel >= 0) ? g_scr[c_sel] : Cext;

    const int tid = threadIdx.x;
    const int lane = tid & 31;
    const int wid = tid >> 5;
    const int warp_m = wid >> 2;        // 0..1
    const int warp_n = wid & 3;         // 0..3
    const int bm = blockIdx.x * 128;
    const int bn = blockIdx.y * 128;

    const int lr = lane & 15;           // ldmatrix row within 16
    const int lh = lane >> 4;           // 16B half select
    const int l7 = lane & 7;            // swizzle term

    float acc[4][4][4];
#pragma unroll
    for (int mt = 0; mt < 4; mt++)
#pragma unroll
        for (int nt = 0; nt < 4; nt++)
#pragma unroll
            for (int j = 0; j < 4; j++) acc[mt][nt][j] = 0.f;

    const __nv_bfloat16* tA_h = Ah + (size_t)bm * EMB;
    const __nv_bfloat16* tA_l = Al + (size_t)bm * EMB;
    const __nv_bfloat16* tB_h = Bh + (size_t)bn * EMB;
    const __nv_bfloat16* tB_l = Bl + (size_t)bn * EMB;

    load_stage(sbase, 0, 0, tid, tA_h, tA_l, tB_h, tB_l);

    const uint32_t arow_off = (uint32_t)(warp_m * 64 + lr) * 128;
    const uint32_t brow_off = (uint32_t)(warp_n * 32 + lr) * 128;

    for (int c = 0; c < 8; ++c) {
        const int buf = c & 1;
        if (c + 1 < 8) {
            load_stage(sbase, buf ^ 1, (c + 1) * 64, tid, tA_h, tA_l, tB_h, tB_l);
            CP_WAIT(1);
        } else {
            CP_WAIT(0);
        }
        __syncthreads();

        const uint32_t sAh = sbase + buf * STAGE_BYTES;
        const uint32_t sAl = sAh + TILE_BYTES;
        const uint32_t sBh = sAh + 2 * TILE_BYTES;
        const uint32_t sBl = sAh + 3 * TILE_BYTES;

#pragma unroll
        for (int kk = 0; kk < 4; kk++) {
            const uint32_t ch = (uint32_t)(((kk * 2) | lh) ^ l7) * 16;
            uint32_t ah[4][4], al[4][4], bh[4][2], bl[4][2];
#pragma unroll
            for (int mt = 0; mt < 4; mt++) {
                uint32_t off = arow_off + (uint32_t)(mt * 16) * 128 + ch;
                ldm_x4(ah[mt][0], ah[mt][1], ah[mt][2], ah[mt][3], sAh + off);
                ldm_x4(al[mt][0], al[mt][1], al[mt][2], al[mt][3], sAl + off);
            }
#pragma unroll
            for (int p = 0; p < 2; p++) {
                uint32_t off = brow_off + (uint32_t)(p * 16) * 128 + ch;
                uint32_t r0, r1, r2, r3;
                // ldmatrix x4 on B rows (n-major): r0=(n0-7,k0-7) r1=(n8-15,k0-7)
                //                                  r2=(n0-7,k8-15) r3=(n8-15,k8-15)
                // m16n8k16 B operand wants {kLo, kHi} per 8-wide n group:
                ldm_x4(r0, r1, r2, r3, sBh + off);
                bh[p * 2][0] = r0; bh[p * 2][1] = r2;
                bh[p * 2 + 1][0] = r1; bh[p * 2 + 1][1] = r3;
                ldm_x4(r0, r1, r2, r3, sBl + off);
                bl[p * 2][0] = r0; bl[p * 2][1] = r2;
                bl[p * 2 + 1][0] = r1; bl[p * 2 + 1][1] = r3;
            }
#pragma unroll
            for (int mt = 0; mt < 4; mt++)
#pragma unroll
                for (int nt = 0; nt < 4; nt++) {
                    mma_bf16(acc[mt][nt], ah[mt], bh[nt]);
                    mma_bf16(acc[mt][nt], ah[mt], bl[nt]);
                    mma_bf16(acc[mt][nt], al[mt], bh[nt]);
                }
        }
        __syncthreads();
    }

    // ---- epilogue: direct STG with bias ----
    const int g = lane >> 2;
    const int tg = lane & 3;
#pragma unroll
    for (int mt = 0; mt < 4; mt++) {
        int row = bm + warp_m * 64 + mt * 16 + g;
#pragma unroll
        for (int nt = 0; nt < 4; nt++) {
            int col = bn + warp_n * 32 + nt * 8 + tg * 2;
            float bx = bias[col], by = bias[col + 1];
            float2 v0 = {acc[mt][nt][0] + bx, acc[mt][nt][1] + by};
            float2 v1 = {acc[mt][nt][2] + bx, acc[mt][nt][3] + by};
            *(float2*)&C[(size_t)row * EMB + col] = v0;
            *(float2*)&C[(size_t)(row + 8) * EMB + col] = v1;
        }
    }
}

// ---------------------------------------------------------------------------
// Banded flash attention (unchanged from R1). One block per (b, h, 64-q tile).
// ---------------------------------------------------------------------------
#define ATTN_SMEM_BYTES ((4 * 4096 + 128) * 4)

__global__ __launch_bounds__(256) void attn_kernel()
{
    extern __shared__ float sm[];
    float* Qs = sm;
    float* Ks = sm + 4096;
    float* Vs = sm + 8192;
    float* Ps = sm + 12288;
    float* scale_s = sm + 16384;
    float* l_s = sm + 16448;

    const int tid = threadIdx.x;
    const int qb = blockIdx.x;
    const int h = blockIdx.y;
    const int b = blockIdx.z;
    const int q0 = qb * 64;
    const int ty = tid >> 4;
    const int tx = tid & 15;

    const float* Q = g_scr[0];
    const float* K = g_scr[1];
    const float* V = g_scr[2];
    const size_t base = (size_t)b * SEQ * EMB + (size_t)h * DHEAD;

#pragma unroll
    for (int l = 0; l < 4; l++) {
        int idx = tid + l * 256;
        int row = idx >> 4;
        int c4 = idx & 15;
        float4 v = *(const float4*)&Q[base + (size_t)(q0 + row) * EMB + c4 * 4];
        Qs[(c4 * 4 + 0) * 64 + row] = v.x;
        Qs[(c4 * 4 + 1) * 64 + row] = v.y;
        Qs[(c4 * 4 + 2) * 64 + row] = v.z;
        Qs[(c4 * 4 + 3) * 64 + row] = v.w;
    }

    float m_run = -1e30f, l_run = 0.f;
    float acc[4][4];
#pragma unroll
    for (int i = 0; i < 4; i++)
#pragma unroll
        for (int j = 0; j < 4; j++) acc[i][j] = 0.f;

    const float rs = 0.044194173824159216f;

    int lo = q0 - WINDOW; if (lo < 0) lo = 0;
    int hi = q0 + 64 + WINDOW; if (hi > SEQ) hi = SEQ;

    __syncthreads();

    for (int kc = lo; kc < hi; kc += 64) {
#pragma unroll
        for (int l = 0; l < 4; l++) {
            int idx = tid + l * 256;
            int row = idx >> 4;
            int c4 = idx & 15;
            float4 kv = *(const float4*)&K[base + (size_t)(kc + row) * EMB + c4 * 4];
            Ks[(c4 * 4 + 0) * 64 + row] = kv.x;
            Ks[(c4 * 4 + 1) * 64 + row] = kv.y;
            Ks[(c4 * 4 + 2) * 64 + row] = kv.z;
            Ks[(c4 * 4 + 3) * 64 + row] = kv.w;
            float4 vv = *(const float4*)&V[base + (size_t)(kc + row) * EMB + c4 * 4];
            *(float4*)&Vs[row * 64 + c4 * 4] = vv;
        }
        __syncthreads();

        float s[4][4];
#pragma unroll
        for (int i = 0; i < 4; i++)
#pragma unroll
            for (int j = 0; j < 4; j++) s[i][j] = 0.f;

#pragma unroll 8
        for (int d = 0; d < 64; d++) {
            float4 a4 = *(const float4*)&Qs[d * 64 + ty * 4];
            float4 b4 = *(const float4*)&Ks[d * 64 + tx * 4];
            float a[4] = {a4.x, a4.y, a4.z, a4.w};
            float bb[4] = {b4.x, b4.y, b4.z, b4.w};
#pragma unroll
            for (int i = 0; i < 4; i++)
#pragma unroll
                for (int j = 0; j < 4; j++)
                    s[i][j] += a[i] * bb[j];
        }

#pragma unroll
        for (int i = 0; i < 4; i++) {
            int qg = q0 + ty * 4 + i;
#pragma unroll
            for (int j = 0; j < 4; j++) {
                int kg = kc + tx * 4 + j;
                int dd = qg - kg; if (dd < 0) dd = -dd;
                float val = (dd <= WINDOW) ? s[i][j] * rs : -1e30f;
                Ps[(tx * 4 + j) * 64 + (ty * 4 + i)] = val;
            }
        }
        __syncthreads();

        if (tid < 64) {
            int q = tid;
            float mo = m_run;
            float mx = mo;
            for (int k2 = 0; k2 < 64; k2++) mx = fmaxf(mx, Ps[k2 * 64 + q]);
            float fac = __expf(mo - mx);
            float l2 = l_run * fac;
            for (int k2 = 0; k2 < 64; k2++) {
                float p = __expf(Ps[k2 * 64 + q] - mx);
                Ps[k2 * 64 + q] = p;
                l2 += p;
            }
            m_run = mx;
            l_run = l2;
            scale_s[q] = fac;
            l_s[q] = l2;
        }
        __syncthreads();

#pragma unroll
        for (int i = 0; i < 4; i++) {
            float f = scale_s[ty * 4 + i];
#pragma unroll
            for (int j = 0; j < 4; j++) acc[i][j] *= f;
        }
#pragma unroll 8
        for (int k2 = 0; k2 < 64; k2++) {
            float4 a4 = *(const float4*)&Ps[k2 * 64 + ty * 4];
            float4 v4 = *(const float4*)&Vs[k2 * 64 + tx * 4];
            float a[4] = {a4.x, a4.y, a4.z, a4.w};
            float vv[4] = {v4.x, v4.y, v4.z, v4.w};
#pragma unroll
            for (int i = 0; i < 4; i++)
#pragma unroll
                for (int j = 0; j < 4; j++)
                    acc[i][j] += a[i] * vv[j];
        }
        __syncthreads();
    }

#pragma unroll
    for (int i = 0; i < 4; i++) {
        int qg = q0 + ty * 4 + i;
        float inv = 1.f / l_s[ty * 4 + i];
        float4 o;
        o.x = acc[i][0] * inv;
        o.y = acc[i][1] * inv;
        o.z = acc[i][2] * inv;
        o.w = acc[i][3] * inv;
        *(float4*)&g_scr[3][(size_t)(b * SEQ + qg) * EMB + h * DHEAD + tx * 4] = o;
    }
}

// ---------------------------------------------------------------------------
extern "C" void kernel_launch(void* const* d_in, const int* in_sizes, int n_in,
                              void* d_out, int out_size)
{
    const float* x  = (const float*)d_in[0];
    const float* Wq = (const float*)d_in[1];
    const float* bq = (const float*)d_in[2];
    const float* Wk = (const float*)d_in[3];
    const float* bk = (const float*)d_in[4];
    const float* Wv = (const float*)d_in[5];
    const float* bv = (const float*)d_in[6];
    const float* Wo = (const float*)d_in[7];
    const float* bo = (const float*)d_in[8];
    float* out = (float*)d_out;

    cudaFuncSetAttribute(gemm_mma, cudaFuncAttributeMaxDynamicSharedMemorySize, GEMM_SMEM);
    cudaFuncSetAttribute(attn_kernel, cudaFuncAttributeMaxDynamicSharedMemorySize,
                         ATTN_SMEM_BYTES);

    // split conversions
    int n4 = MTOT * EMB / 4;
    int w4 = EMB * EMB / 4;
    conv_split<<<(n4 + 255) / 256, 256>>>(x, -1, 0, n4);
    conv_split<<<(w4 + 255) / 256, 256>>>(Wq, -1, 2, w4);
    conv_split<<<(w4 + 255) / 256, 256>>>(Wk, -1, 3, w4);
    conv_split<<<(w4 + 255) / 256, 256>>>(Wv, -1, 4, w4);
    conv_split<<<(w4 + 255) / 256, 256>>>(Wo, -1, 5, w4);

    dim3 gg(MTOT / 128, EMB / 128);
    gemm_mma<<<gg, 256, GEMM_SMEM>>>(bq, nullptr, 0, 0, 0);
    gemm_mma<<<gg, 256, GEMM_SMEM>>>(bk, nullptr, 0, 1, 1);
    gemm_mma<<<gg, 256, GEMM_SMEM>>>(bv, nullptr, 0, 2, 2);

    attn_kernel<<<dim3(SEQ / 64, NHEAD, BATCH), 256, ATTN_SMEM_BYTES>>>();

    conv_split<<<(n4 + 255) / 256, 256>>>(nullptr, 3, 1, n4);
    gemm_mma<<<gg, 256, GEMM_SMEM>>>(bo, out, 1, 3, -1);
}

// round 6
// speedup vs baseline: 2.3463x; 1.4994x over previous
#include <cuda_runtime.h>
#include <cuda_bf16.h>
#include <math.h>
#include <stdint.h>

#define EMB 512
#define NHEAD 8
#define DHEAD 64
#define SEQ 4096
#define BATCH 2
#define WINDOW 128
#define MTOT (BATCH * SEQ)   // 8192

// bf16 hi/lo operand arrays ([token][EMB] layout)
__device__ __nv_bfloat16 g_xhi[(size_t)MTOT * EMB];
__device__ __nv_bfloat16 g_xlo[(size_t)MTOT * EMB];
__device__ __nv_bfloat16 g_qhi[(size_t)MTOT * EMB];
__device__ __nv_bfloat16 g_qlo[(size_t)MTOT * EMB];
__device__ __nv_bfloat16 g_khi[(size_t)MTOT * EMB];
__device__ __nv_bfloat16 g_klo[(size_t)MTOT * EMB];
__device__ __nv_bfloat16 g_vhi[(size_t)MTOT * EMB];
__device__ __nv_bfloat16 g_vlo[(size_t)MTOT * EMB];
__device__ __nv_bfloat16 g_ohi[(size_t)MTOT * EMB];
__device__ __nv_bfloat16 g_olo[(size_t)MTOT * EMB];
__device__ __nv_bfloat16 g_whi[4][EMB * EMB];
__device__ __nv_bfloat16 g_wlo[4][EMB * EMB];

// ---------------------------------------------------------------------------
// helpers (base sm_103 ISA: cp.async + ldmatrix + mma.sync)
// ---------------------------------------------------------------------------
static __device__ __forceinline__ uint32_t smem_u32(const void* p) {
    uint32_t a;
    asm("{ .reg .u64 t; cvta.to.shared.u64 t, %1; cvt.u32.u64 %0, t; }"
        : "=r"(a) : "l"(p));
    return a;
}
static __device__ __forceinline__ void cp16(uint32_t dst, const void* src) {
    asm volatile("cp.async.cg.shared.global [%0], [%1], 16;" :: "r"(dst), "l"(src));
}
#define CP_COMMIT() asm volatile("cp.async.commit_group;" ::: "memory")
#define CP_WAIT(n)  asm volatile("cp.async.wait_group %0;" :: "n"(n) : "memory")

static __device__ __forceinline__ void ldm_x4(uint32_t& r0, uint32_t& r1,
                                              uint32_t& r2, uint32_t& r3, uint32_t a) {
    asm volatile("ldmatrix.sync.aligned.m8n8.x4.shared.b16 {%0,%1,%2,%3}, [%4];"
                 : "=r"(r0), "=r"(r1), "=r"(r2), "=r"(r3) : "r"(a));
}
static __device__ __forceinline__ void mma_bf16(float* d, const uint32_t* a, const uint32_t* b) {
    asm volatile(
        "mma.sync.aligned.m16n8k16.row.col.f32.bf16.bf16.f32 "
        "{%0,%1,%2,%3}, {%4,%5,%6,%7}, {%8,%9}, {%0,%1,%2,%3};"
        : "+f"(d[0]), "+f"(d[1]), "+f"(d[2]), "+f"(d[3])
        : "r"(a[0]), "r"(a[1]), "r"(a[2]), "r"(a[3]), "r"(b[0]), "r"(b[1]));
}
static __device__ __forceinline__ uint32_t pack_h(__nv_bfloat16 a, __nv_bfloat16 b) {
    __nv_bfloat162 t; t.x = a; t.y = b;   // x = low 16 bits (element k), y = high (k+1)
    return *(uint32_t*)&t;
}

// ---------------------------------------------------------------------------
// fp32 -> bf16 hi/lo split.  dst_sel: 0 -> x, 2..5 -> W[dst_sel-2]
// ---------------------------------------------------------------------------
__global__ __launch_bounds__(256) void conv_split(
    const float* __restrict__ src, int dst_sel, int n4)
{
    int i = blockIdx.x * blockDim.x + threadIdx.x;
    if (i >= n4) return;
    __nv_bfloat16 *hi, *lo;
    if (dst_sel == 0) { hi = g_xhi; lo = g_xlo; }
    else              { hi = g_whi[dst_sel - 2]; lo = g_wlo[dst_sel - 2]; }

    float4 v = ((const float4*)src)[i];
    float f[4] = {v.x, v.y, v.z, v.w};
    __align__(8) __nv_bfloat16 h[4], l[4];
#pragma unroll
    for (int j = 0; j < 4; j++) {
        h[j] = __float2bfloat16(f[j]);
        l[j] = __float2bfloat16(f[j] - __bfloat162float(h[j]));
    }
    ((uint2*)hi)[i] = *(uint2*)h;
    ((uint2*)lo)[i] = *(uint2*)l;
}

// ---------------------------------------------------------------------------
// HMMA GEMM: C[m,n] = sum_k A[m,k]*W[n,k] + bias[n],  M=8192, N=K=512
// 3-pass bf16 hi/lo split, fp32 accum. 128x128 tile, K-chunk 64, 8 warps.
// c_sel: 0/1/2 -> write bf16 hi/lo (Q/K/V); -1 -> fp32 to Cext.
// a_sel: 0 -> x splits, 1 -> attn-out splits.
// ---------------------------------------------------------------------------
#define TILE_BYTES 16384
#define STAGE_BYTES (4 * TILE_BYTES)
#define GEMM_SMEM (2 * STAGE_BYTES)

static __device__ __forceinline__ void load_stage(
    uint32_t sbase, int buf, int k0, int tid,
    const __nv_bfloat16* t0, const __nv_bfloat16* t1,
    const __nv_bfloat16* t2, const __nv_bfloat16* t3)
{
    const __nv_bfloat16* tsrc[4] = {t0, t1, t2, t3};
    uint32_t stb = sbase + (uint32_t)buf * STAGE_BYTES;
#pragma unroll
    for (int i = 0; i < 16; i++) {
        int t = i >> 2;
        int idx = tid + i * 256;
        int rr = (idx >> 3) & 127;
        int cc = idx & 7;
        uint32_t dst = stb + t * TILE_BYTES + rr * 128 + ((cc ^ (rr & 7)) * 16);
        cp16(dst, tsrc[t] + (size_t)rr * EMB + k0 + cc * 8);
    }
    CP_COMMIT();
}

__global__ __launch_bounds__(256, 1) void gemm_mma(
    const float* __restrict__ bias, float* __restrict__ Cext,
    int a_sel, int w_idx, int c_sel)
{
    extern __shared__ __align__(1024) char dsm[];
    const uint32_t sbase = smem_u32(dsm);

    const __nv_bfloat16* Ah = a_sel ? g_ohi : g_xhi;
    const __nv_bfloat16* Al = a_sel ? g_olo : g_xlo;
    const __nv_bfloat16* Bh = g_whi[w_idx];
    const __nv_bfloat16* Bl = g_wlo[w_idx];

    const int tid = threadIdx.x;
    const int lane = tid & 31;
    const int wid = tid >> 5;
    const int warp_m = wid >> 2;
    const int warp_n = wid & 3;
    const int bm = blockIdx.x * 128;
    const int bn = blockIdx.y * 128;

    const int lr = lane & 15;
    const int lh = lane >> 4;
    const int l7 = lane & 7;

    float acc[4][4][4];
#pragma unroll
    for (int mt = 0; mt < 4; mt++)
#pragma unroll
        for (int nt = 0; nt < 4; nt++)
#pragma unroll
            for (int j = 0; j < 4; j++) acc[mt][nt][j] = 0.f;

    const __nv_bfloat16* tA_h = Ah + (size_t)bm * EMB;
    const __nv_bfloat16* tA_l = Al + (size_t)bm * EMB;
    const __nv_bfloat16* tB_h = Bh + (size_t)bn * EMB;
    const __nv_bfloat16* tB_l = Bl + (size_t)bn * EMB;

    load_stage(sbase, 0, 0, tid, tA_h, tA_l, tB_h, tB_l);

    const uint32_t arow_off = (uint32_t)(warp_m * 64 + lr) * 128;
    const uint32_t brow_off = (uint32_t)(warp_n * 32 + lr) * 128;

    for (int c = 0; c < 8; ++c) {
        const int buf = c & 1;
        if (c + 1 < 8) {
            load_stage(sbase, buf ^ 1, (c + 1) * 64, tid, tA_h, tA_l, tB_h, tB_l);
            CP_WAIT(1);
        } else {
            CP_WAIT(0);
        }
        __syncthreads();

        const uint32_t sAh = sbase + buf * STAGE_BYTES;
        const uint32_t sAl = sAh + TILE_BYTES;
        const uint32_t sBh = sAh + 2 * TILE_BYTES;
        const uint32_t sBl = sAh + 3 * TILE_BYTES;

#pragma unroll
        for (int kk = 0; kk < 4; kk++) {
            const uint32_t ch = (uint32_t)(((kk * 2) | lh) ^ l7) * 16;
            uint32_t ah[4][4], al[4][4], bh[4][2], bl[4][2];
#pragma unroll
            for (int mt = 0; mt < 4; mt++) {
                uint32_t off = arow_off + (uint32_t)(mt * 16) * 128 + ch;
                ldm_x4(ah[mt][0], ah[mt][1], ah[mt][2], ah[mt][3], sAh + off);
                ldm_x4(al[mt][0], al[mt][1], al[mt][2], al[mt][3], sAl + off);
            }
#pragma unroll
            for (int p = 0; p < 2; p++) {
                uint32_t off = brow_off + (uint32_t)(p * 16) * 128 + ch;
                uint32_t r0, r1, r2, r3;
                ldm_x4(r0, r1, r2, r3, sBh + off);
                bh[p * 2][0] = r0; bh[p * 2][1] = r2;
                bh[p * 2 + 1][0] = r1; bh[p * 2 + 1][1] = r3;
                ldm_x4(r0, r1, r2, r3, sBl + off);
                bl[p * 2][0] = r0; bl[p * 2][1] = r2;
                bl[p * 2 + 1][0] = r1; bl[p * 2 + 1][1] = r3;
            }
#pragma unroll
            for (int mt = 0; mt < 4; mt++)
#pragma unroll
                for (int nt = 0; nt < 4; nt++) {
                    mma_bf16(acc[mt][nt], ah[mt], bh[nt]);
                    mma_bf16(acc[mt][nt], ah[mt], bl[nt]);
                    mma_bf16(acc[mt][nt], al[mt], bh[nt]);
                }
        }
        __syncthreads();
    }

    // ---- epilogue ----
    __nv_bfloat16* Chi = nullptr;
    __nv_bfloat16* Clo = nullptr;
    if (c_sel == 0)      { Chi = g_qhi; Clo = g_qlo; }
    else if (c_sel == 1) { Chi = g_khi; Clo = g_klo; }
    else if (c_sel == 2) { Chi = g_vhi; Clo = g_vlo; }

    const int g = lane >> 2;
    const int tg = lane & 3;
#pragma unroll
    for (int mt = 0; mt < 4; mt++) {
        int row = bm + warp_m * 64 + mt * 16 + g;
#pragma unroll
        for (int nt = 0; nt < 4; nt++) {
            int col = bn + warp_n * 32 + nt * 8 + tg * 2;
            float bx = bias[col], by = bias[col + 1];
            float v00 = acc[mt][nt][0] + bx, v01 = acc[mt][nt][1] + by;
            float v10 = acc[mt][nt][2] + bx, v11 = acc[mt][nt][3] + by;
            if (c_sel < 0) {
                float2 a0 = {v00, v01}, a1 = {v10, v11};
                *(float2*)&Cext[(size_t)row * EMB + col] = a0;
                *(float2*)&Cext[(size_t)(row + 8) * EMB + col] = a1;
            } else {
                __nv_bfloat16 h00 = __float2bfloat16(v00);
                __nv_bfloat16 h01 = __float2bfloat16(v01);
                __nv_bfloat16 h10 = __float2bfloat16(v10);
                __nv_bfloat16 h11 = __float2bfloat16(v11);
                *(uint32_t*)&Chi[(size_t)row * EMB + col] = pack_h(h00, h01);
                *(uint32_t*)&Chi[(size_t)(row + 8) * EMB + col] = pack_h(h10, h11);
                __nv_bfloat16 l00 = __float2bfloat16(v00 - __bfloat162float(h00));
                __nv_bfloat16 l01 = __float2bfloat16(v01 - __bfloat162float(h01));
                __nv_bfloat16 l10 = __float2bfloat16(v10 - __bfloat162float(h10));
                __nv_bfloat16 l11 = __float2bfloat16(v11 - __bfloat162float(h11));
                *(uint32_t*)&Clo[(size_t)row * EMB + col] = pack_h(l00, l01);
                *(uint32_t*)&Clo[(size_t)(row + 8) * EMB + col] = pack_h(l10, l11);
            }
        }
    }
}

// ---------------------------------------------------------------------------
// HMMA banded flash attention. One CTA per (b, h, 64-query tile), 4 warps.
// Warp w owns queries [q0 + w*16, q0 + w*16 + 16).
// smem: region K (16KB: hi 0..8K, lo 8..16K; also Q staging), region Vt (16KB).
// Tiles 64 rows x 128B, same swizzle as the GEMM.
// ---------------------------------------------------------------------------
__global__ __launch_bounds__(128) void attn_mma()
{
    __shared__ __align__(1024) char smem_buf[32768];
    char* sK = smem_buf;
    char* sV = smem_buf + 16384;
    const uint32_t bK = smem_u32(sK);
    const uint32_t bV = smem_u32(sV);

    const int tid = threadIdx.x;
    const int lane = tid & 31;
    const int wid = tid >> 5;
    const int q0 = blockIdx.x * 64;
    const int h = blockIdx.y;
    const int b = blockIdx.z;

    const int lr = lane & 15;
    const int lh = lane >> 4;
    const int l7 = lane & 7;
    const int g = lane >> 2;
    const int tg = lane & 3;

    const size_t tok0 = (size_t)b * SEQ;
    const int colh = h * DHEAD;

    // ---- stage Q into sK region, load fragments, then free for K ----
#pragma unroll
    for (int i = 0; i < 8; i++) {
        int t = i >> 2;
        int idx = tid + (i & 3) * 128;
        int rr = idx >> 3, cc = idx & 7;
        const __nv_bfloat16* src =
            (t ? g_qlo : g_qhi) + (tok0 + q0 + rr) * EMB + colh + cc * 8;
        cp16(bK + t * 8192 + rr * 128 + ((cc ^ (rr & 7)) * 16), src);
    }
    CP_COMMIT(); CP_WAIT(0); __syncthreads();

    uint32_t qh[4][4], ql[4][4];
#pragma unroll
    for (int kk = 0; kk < 4; kk++) {
        uint32_t ch = (uint32_t)(((kk * 2) | lh) ^ l7) * 16;
        uint32_t off = (uint32_t)(wid * 16 + lr) * 128 + ch;
        ldm_x4(qh[kk][0], qh[kk][1], qh[kk][2], qh[kk][3], bK + off);
        ldm_x4(ql[kk][0], ql[kk][1], ql[kk][2], ql[kk][3], bK + 8192 + off);
    }
    __syncthreads();

    float oacc[8][4];
#pragma unroll
    for (int j = 0; j < 8; j++)
#pragma unroll
        for (int c = 0; c < 4; c++) oacc[j][c] = 0.f;

    float m0 = -1e30f, m8 = -1e30f, l0 = 0.f, l8 = 0.f;
    const float rs = 0.044194173824159216f;  // 1/sqrt(512)

    const int qg0 = q0 + wid * 16 + g;
    const int qg8 = qg0 + 8;

    int klo_ = q0 - WINDOW; if (klo_ < 0) klo_ = 0;
    int khi_ = q0 + 64 + WINDOW; if (khi_ > SEQ) khi_ = SEQ;

    for (int kc = klo_; kc < khi_; kc += 64) {
        // ---- K chunk via cp.async (swizzled) ----
#pragma unroll
        for (int i = 0; i < 8; i++) {
            int t = i >> 2;
            int idx = tid + (i & 3) * 128;
            int rr = idx >> 3, cc = idx & 7;
            const __nv_bfloat16* src =
                (t ? g_klo : g_khi) + (tok0 + kc + rr) * EMB + colh + cc * 8;
            cp16(bK + t * 8192 + rr * 128 + ((cc ^ (rr & 7)) * 16), src);
        }
        CP_COMMIT();
        // ---- V chunk: load [key][dim], transpose into Vt[dim][key] ----
#pragma unroll
        for (int t = 0; t < 2; t++) {
            const __nv_bfloat16* vsrc = t ? g_vlo : g_vhi;
            char* vdst = sV + t * 8192;
#pragma unroll
            for (int i = 0; i < 4; i++) {
                int idx = tid + i * 128;
                int key = idx & 63, dg = idx >> 6;  // dg 0..7 covers 64 dims
                __align__(16) __nv_bfloat16 e[8];
                *(uint4*)e = *(const uint4*)(vsrc + (tok0 + kc + key) * EMB + colh + dg * 8);
#pragma unroll
                for (int ee = 0; ee < 8; ee++) {
                    int d = dg * 8 + ee;
                    *(__nv_bfloat16*)(vdst + d * 128 + (((key >> 3) ^ (d & 7)) * 16)
                                      + (key & 7) * 2) = e[ee];
                }
            }
        }
        CP_WAIT(0);
        __syncthreads();

        // ---- S = Q K^T (3-pass split) ----
        float sacc[8][4];
#pragma unroll
        for (int j = 0; j < 8; j++)
#pragma unroll
            for (int c = 0; c < 4; c++) sacc[j][c] = 0.f;

#pragma unroll
        for (int kk = 0; kk < 4; kk++) {
            uint32_t ch = (uint32_t)(((kk * 2) | lh) ^ l7) * 16;
            uint32_t bh[8][2], bl[8][2];
#pragma unroll
            for (int p = 0; p < 4; p++) {
                uint32_t off = (uint32_t)(p * 16 + lr) * 128 + ch;
                uint32_t r0, r1, r2, r3;
                ldm_x4(r0, r1, r2, r3, bK + off);
                bh[p * 2][0] = r0; bh[p * 2][1] = r2;
                bh[p * 2 + 1][0] = r1; bh[p * 2 + 1][1] = r3;
                ldm_x4(r0, r1, r2, r3, bK + 8192 + off);
                bl[p * 2][0] = r0; bl[p * 2][1] = r2;
                bl[p * 2 + 1][0] = r1; bl[p * 2 + 1][1] = r3;
            }
#pragma unroll
            for (int j = 0; j < 8; j++) {
                mma_bf16(sacc[j], qh[kk], bh[j]);
                mma_bf16(sacc[j], qh[kk], bl[j]);
                mma_bf16(sacc[j], ql[kk], bh[j]);
            }
        }

        // ---- mask + scale + row max ----
        float tmx0 = -1e30f, tmx8 = -1e30f;
#pragma unroll
        for (int j = 0; j < 8; j++) {
            int kg = kc + j * 8 + tg * 2;
            float s0 = sacc[j][0] * rs, s1 = sacc[j][1] * rs;
            float s2 = sacc[j][2] * rs, s3 = sacc[j][3] * rs;
            int d00 = qg0 - kg,     d01 = qg0 - (kg + 1);
            int d10 = qg8 - kg,     d11 = qg8 - (kg + 1);
            if (abs(d00) > WINDOW) s0 = -1e30f;
            if (abs(d01) > WINDOW) s1 = -1e30f;
            if (abs(d10) > WINDOW) s2 = -1e30f;
            if (abs(d11) > WINDOW) s3 = -1e30f;
            sacc[j][0] = s0; sacc[j][1] = s1; sacc[j][2] = s2; sacc[j][3] = s3;
            tmx0 = fmaxf(tmx0, fmaxf(s0, s1));
            tmx8 = fmaxf(tmx8, fmaxf(s2, s3));
        }
        tmx0 = fmaxf(tmx0, __shfl_xor_sync(0xffffffffu, tmx0, 1));
        tmx0 = fmaxf(tmx0, __shfl_xor_sync(0xffffffffu, tmx0, 2));
        tmx8 = fmaxf(tmx8, __shfl_xor_sync(0xffffffffu, tmx8, 1));
        tmx8 = fmaxf(tmx8, __shfl_xor_sync(0xffffffffu, tmx8, 2));

        float mn0 = fmaxf(m0, tmx0), mn8 = fmaxf(m8, tmx8);
        float f0 = __expf(m0 - mn0), f8 = __expf(m8 - mn8);

        // ---- exp, split to bf16 hi/lo P fragments, row sums ----
        float ls0 = 0.f, ls8 = 0.f;
        uint32_t phg[8], phg8[8], plg[8], plg8[8];
#pragma unroll
        for (int j = 0; j < 8; j++) {
            float p0 = __expf(sacc[j][0] - mn0);
            float p1 = __expf(sacc[j][1] - mn0);
            float p2 = __expf(sacc[j][2] - mn8);
            float p3 = __expf(sacc[j][3] - mn8);
            ls0 += p0 + p1; ls8 += p2 + p3;
            __nv_bfloat16 h0 = __float2bfloat16(p0);
            __nv_bfloat16 h1 = __float2bfloat16(p1);
            __nv_bfloat16 h2 = __float2bfloat16(p2);
            __nv_bfloat16 h3 = __float2bfloat16(p3);
            phg[j]  = pack_h(h0, h1);
            phg8[j] = pack_h(h2, h3);
            plg[j]  = pack_h(__float2bfloat16(p0 - __bfloat162float(h0)),
                             __float2bfloat16(p1 - __bfloat162float(h1)));
            plg8[j] = pack_h(__float2bfloat16(p2 - __bfloat162float(h2)),
                             __float2bfloat16(p3 - __bfloat162float(h3)));
        }
        ls0 += __shfl_xor_sync(0xffffffffu, ls0, 1);
        ls0 += __shfl_xor_sync(0xffffffffu, ls0, 2);
        ls8 += __shfl_xor_sync(0xffffffffu, ls8, 1);
        ls8 += __shfl_xor_sync(0xffffffffu, ls8, 2);
        l0 = l0 * f0 + ls0;
        l8 = l8 * f8 + ls8;
        m0 = mn0; m8 = mn8;

        // rescale output accumulators
#pragma unroll
        for (int j = 0; j < 8; j++) {
            oacc[j][0] *= f0; oacc[j][1] *= f0;
            oacc[j][2] *= f8; oacc[j][3] *= f8;
        }

        // ---- O += P V (3-pass split), B from transposed V ----
#pragma unroll
        for (int t = 0; t < 4; t++) {
            uint32_t ch = (uint32_t)(((t * 2) | lh) ^ l7) * 16;
            uint32_t vh[8][2], vl[8][2];
#pragma unroll
            for (int p = 0; p < 4; p++) {
                uint32_t off = (uint32_t)(p * 16 + lr) * 128 + ch;
                uint32_t r0, r1, r2, r3;
                ldm_x4(r0, r1, r2, r3, bV + off);
                vh[p * 2][0] = r0; vh[p * 2][1] = r2;
                vh[p * 2 + 1][0] = r1; vh[p * 2 + 1][1] = r3;
                ldm_x4(r0, r1, r2, r3, bV + 8192 + off);
                vl[p * 2][0] = r0; vl[p * 2][1] = r2;
                vl[p * 2 + 1][0] = r1; vl[p * 2 + 1][1] = r3;
            }
            uint32_t pa_h[4] = {phg[2 * t], phg8[2 * t], phg[2 * t + 1], phg8[2 * t + 1]};
            uint32_t pa_l[4] = {plg[2 * t], plg8[2 * t], plg[2 * t + 1], plg8[2 * t + 1]};
#pragma unroll
            for (int j = 0; j < 8; j++) {
                mma_bf16(oacc[j], pa_h, vh[j]);
                mma_bf16(oacc[j], pa_l, vh[j]);
                mma_bf16(oacc[j], pa_h, vl[j]);
            }
        }
        __syncthreads();
    }

    // ---- epilogue: normalize, split to hi/lo, store ----
    float il0 = 1.f / l0, il8 = 1.f / l8;
    size_t r0base = (tok0 + qg0) * EMB + colh;
    size_t r8base = (tok0 + qg8) * EMB + colh;
#pragma unroll
    for (int j = 0; j < 8; j++) {
        int col = j * 8 + tg * 2;
        float v00 = oacc[j][0] * il0, v01 = oacc[j][1] * il0;
        float v10 = oacc[j][2] * il8, v11 = oacc[j][3] * il8;
        __nv_bfloat16 h00 = __float2bfloat16(v00);
        __nv_bfloat16 h01 = __float2bfloat16(v01);
        __nv_bfloat16 h10 = __float2bfloat16(v10);
        __nv_bfloat16 h11 = __float2bfloat16(v11);
        *(uint32_t*)&g_ohi[r0base + col] = pack_h(h00, h01);
        *(uint32_t*)&g_ohi[r8base + col] = pack_h(h10, h11);
        *(uint32_t*)&g_olo[r0base + col] =
            pack_h(__float2bfloat16(v00 - __bfloat162float(h00)),
                   __float2bfloat16(v01 - __bfloat162float(h01)));
        *(uint32_t*)&g_olo[r8base + col] =
            pack_h(__float2bfloat16(v10 - __bfloat162float(h10)),
                   __float2bfloat16(v11 - __bfloat162float(h11)));
    }
}

// ---------------------------------------------------------------------------
extern "C" void kernel_launch(void* const* d_in, const int* in_sizes, int n_in,
                              void* d_out, int out_size)
{
    const float* x  = (const float*)d_in[0];
    const float* Wq = (const float*)d_in[1];
    const float* bq = (const float*)d_in[2];
    const float* Wk = (const float*)d_in[3];
    const float* bk = (const float*)d_in[4];
    const float* Wv = (const float*)d_in[5];
    const float* bv = (const float*)d_in[6];
    const float* Wo = (const float*)d_in[7];
    const float* bo = (const float*)d_in[8];
    float* out = (float*)d_out;

    cudaFuncSetAttribute(gemm_mma, cudaFuncAttributeMaxDynamicSharedMemorySize, GEMM_SMEM);

    int n4 = MTOT * EMB / 4;
    int w4 = EMB * EMB / 4;
    conv_split<<<(n4 + 255) / 256, 256>>>(x, 0, n4);
    conv_split<<<(w4 + 255) / 256, 256>>>(Wq, 2, w4);
    conv_split<<<(w4 + 255) / 256, 256>>>(Wk, 3, w4);
    conv_split<<<(w4 + 255) / 256, 256>>>(Wv, 4, w4);
    conv_split<<<(w4 + 255) / 256, 256>>>(Wo, 5, w4);

    dim3 gg(MTOT / 128, EMB / 128);
    gemm_mma<<<gg, 256, GEMM_SMEM>>>(bq, nullptr, 0, 0, 0);
    gemm_mma<<<gg, 256, GEMM_SMEM>>>(bk, nullptr, 0, 1, 1);
    gemm_mma<<<gg, 256, GEMM_SMEM>>>(bv, nullptr, 0, 2, 2);

    attn_mma<<<dim3(SEQ / 64, NHEAD, BATCH), 128>>>();

    gemm_mma<<<gg, 256, GEMM_SMEM>>>(bo, out, 1, 3, -1);
}

// round 7
// speedup vs baseline: 3.3055x; 1.4088x over previous
#include <cuda_runtime.h>
#include <cuda_fp16.h>
#include <math.h>
#include <stdint.h>

#define EMB 512
#define NHEAD 8
#define DHEAD 64
#define SEQ 4096
#define BATCH 2
#define WINDOW 128
#define MTOT (BATCH * SEQ)   // 8192

// fp16 operands ([token][EMB] layout)
__device__ __half g_xhi[(size_t)MTOT * EMB];
__device__ __half g_xlo[(size_t)MTOT * EMB];
__device__ __half g_qhi[(size_t)MTOT * EMB];
__device__ __half g_qlo[(size_t)MTOT * EMB];
__device__ __half g_kh [(size_t)MTOT * EMB];
__device__ __half g_vh [(size_t)MTOT * EMB];
__device__ __half g_ohi[(size_t)MTOT * EMB];
__device__ __half g_olo[(size_t)MTOT * EMB];
__device__ __half g_w[4][EMB * EMB];          // plain fp16 weights

// ---------------------------------------------------------------------------
// helpers (base sm_103 ISA: cp.async + ldmatrix + mma.sync)
// ---------------------------------------------------------------------------
static __device__ __forceinline__ uint32_t smem_u32(const void* p) {
    uint32_t a;
    asm("{ .reg .u64 t; cvta.to.shared.u64 t, %1; cvt.u32.u64 %0, t; }"
        : "=r"(a) : "l"(p));
    return a;
}
static __device__ __forceinline__ void cp16(uint32_t dst, const void* src) {
    asm volatile("cp.async.cg.shared.global [%0], [%1], 16;" :: "r"(dst), "l"(src));
}
#define CP_COMMIT() asm volatile("cp.async.commit_group;" ::: "memory")
#define CP_WAIT(n)  asm volatile("cp.async.wait_group %0;" :: "n"(n) : "memory")

static __device__ __forceinline__ void ldm_x4(uint32_t& r0, uint32_t& r1,
                                              uint32_t& r2, uint32_t& r3, uint32_t a) {
    asm volatile("ldmatrix.sync.aligned.m8n8.x4.shared.b16 {%0,%1,%2,%3}, [%4];"
                 : "=r"(r0), "=r"(r1), "=r"(r2), "=r"(r3) : "r"(a));
}
static __device__ __forceinline__ void mma_f16(float* d, const uint32_t* a, const uint32_t* b) {
    asm volatile(
        "mma.sync.aligned.m16n8k16.row.col.f32.f16.f16.f32 "
        "{%0,%1,%2,%3}, {%4,%5,%6,%7}, {%8,%9}, {%0,%1,%2,%3};"
        : "+f"(d[0]), "+f"(d[1]), "+f"(d[2]), "+f"(d[3])
        : "r"(a[0]), "r"(a[1]), "r"(a[2]), "r"(a[3]), "r"(b[0]), "r"(b[1]));
}
static __device__ __forceinline__ uint32_t pack_h(__half a, __half b) {
    __half2 t; t.x = a; t.y = b;
    return *(uint32_t*)&t;
}

// ---------------------------------------------------------------------------
// conversions
// ---------------------------------------------------------------------------
__global__ __launch_bounds__(256) void conv_x(const float* __restrict__ src, int n4)
{
    int i = blockIdx.x * blockDim.x + threadIdx.x;
    if (i >= n4) return;
    float4 v = ((const float4*)src)[i];
    float f[4] = {v.x, v.y, v.z, v.w};
    __align__(8) __half h[4], l[4];
#pragma unroll
    for (int j = 0; j < 4; j++) {
        h[j] = __float2half(f[j]);
        l[j] = __float2half(f[j] - __half2float(h[j]));
    }
    ((uint2*)g_xhi)[i] = *(uint2*)h;
    ((uint2*)g_xlo)[i] = *(uint2*)l;
}

__global__ __launch_bounds__(256) void conv_w(
    const float* __restrict__ w0, const float* __restrict__ w1,
    const float* __restrict__ w2, const float* __restrict__ w3, int n4)
{
    int i = blockIdx.x * blockDim.x + threadIdx.x;
    if (i >= n4) return;
    const float* srcs[4] = {w0, w1, w2, w3};
    const float* src = srcs[blockIdx.y];
    __half* dst = g_w[blockIdx.y];
    float4 v = ((const float4*)src)[i];
    __align__(8) __half h[4];
    h[0] = __float2half(v.x); h[1] = __float2half(v.y);
    h[2] = __float2half(v.z); h[3] = __float2half(v.w);
    ((uint2*)dst)[i] = *(uint2*)h;
}

// ---------------------------------------------------------------------------
// HMMA GEMM: C[m,n] = sum_k A[m,k]*W[n,k] + bias[n],  M=8192, N=K=512
// 2-pass fp16: A = Ah + Al (fp16 split), W plain fp16, fp32 accum.
// 128x128 tile, K-chunk 64, double buffer, 8 warps (2Mx4N).
// fused QKV: grid (64, 4, 3); final: grid (64, 4, 1), fin=1.
// ---------------------------------------------------------------------------
#define TILE_BYTES 16384            // 128 rows x 128B
#define STAGE_BYTES (3 * TILE_BYTES) // Ah, Al, W
#define GEMM_SMEM (2 * STAGE_BYTES)  // 96 KB

static __device__ __forceinline__ void load_stage(
    uint32_t sbase, int buf, int k0, int tid,
    const __half* t0, const __half* t1, const __half* t2)
{
    const __half* tsrc[3] = {t0, t1, t2};
    uint32_t stb = sbase + (uint32_t)buf * STAGE_BYTES;
#pragma unroll
    for (int i = 0; i < 12; i++) {
        int t = i >> 2;
        int idx = tid + i * 256;
        int rr = (idx >> 3) & 127;
        int cc = idx & 7;
        uint32_t dst = stb + t * TILE_BYTES + rr * 128 + ((cc ^ (rr & 7)) * 16);
        cp16(dst, tsrc[t] + (size_t)rr * EMB + k0 + cc * 8);
    }
    CP_COMMIT();
}

__global__ __launch_bounds__(256, 1) void gemm_mma(
    const float* __restrict__ b0, const float* __restrict__ b1,
    const float* __restrict__ b2, float* __restrict__ Cext, int fin)
{
    extern __shared__ __align__(1024) char dsm[];
    const uint32_t sbase = smem_u32(dsm);

    const int z = blockIdx.z;
    const int w_idx = fin ? 3 : z;
    const float* bias = fin ? b0 : (z == 0 ? b0 : (z == 1 ? b1 : b2));
    const __half* Ah = fin ? g_ohi : g_xhi;
    const __half* Al = fin ? g_olo : g_xlo;
    const __half* Bw = g_w[w_idx];

    const int tid = threadIdx.x;
    const int lane = tid & 31;
    const int wid = tid >> 5;
    const int warp_m = wid >> 2;
    const int warp_n = wid & 3;
    const int bm = blockIdx.x * 128;
    const int bn = blockIdx.y * 128;

    const int lr = lane & 15;
    const int lh = lane >> 4;
    const int l7 = lane & 7;

    float acc[4][4][4];
#pragma unroll
    for (int mt = 0; mt < 4; mt++)
#pragma unroll
        for (int nt = 0; nt < 4; nt++)
#pragma unroll
            for (int j = 0; j < 4; j++) acc[mt][nt][j] = 0.f;

    const __half* tA_h = Ah + (size_t)bm * EMB;
    const __half* tA_l = Al + (size_t)bm * EMB;
    const __half* tB   = Bw + (size_t)bn * EMB;

    load_stage(sbase, 0, 0, tid, tA_h, tA_l, tB);

    const uint32_t arow_off = (uint32_t)(warp_m * 64 + lr) * 128;
    const uint32_t brow_off = (uint32_t)(warp_n * 32 + lr) * 128;

    for (int c = 0; c < 8; ++c) {
        const int buf = c & 1;
        if (c + 1 < 8) {
            load_stage(sbase, buf ^ 1, (c + 1) * 64, tid, tA_h, tA_l, tB);
            CP_WAIT(1);
        } else {
            CP_WAIT(0);
        }
        __syncthreads();

        const uint32_t sAh = sbase + buf * STAGE_BYTES;
        const uint32_t sAl = sAh + TILE_BYTES;
        const uint32_t sB  = sAh + 2 * TILE_BYTES;

#pragma unroll
        for (int kk = 0; kk < 4; kk++) {
            const uint32_t ch = (uint32_t)(((kk * 2) | lh) ^ l7) * 16;
            uint32_t ah[4][4], al[4][4], bh[4][2];
#pragma unroll
            for (int mt = 0; mt < 4; mt++) {
                uint32_t off = arow_off + (uint32_t)(mt * 16) * 128 + ch;
                ldm_x4(ah[mt][0], ah[mt][1], ah[mt][2], ah[mt][3], sAh + off);
                ldm_x4(al[mt][0], al[mt][1], al[mt][2], al[mt][3], sAl + off);
            }
#pragma unroll
            for (int p = 0; p < 2; p++) {
                uint32_t off = brow_off + (uint32_t)(p * 16) * 128 + ch;
                uint32_t r0, r1, r2, r3;
                ldm_x4(r0, r1, r2, r3, sB + off);
                bh[p * 2][0] = r0; bh[p * 2][1] = r2;
                bh[p * 2 + 1][0] = r1; bh[p * 2 + 1][1] = r3;
            }
#pragma unroll
            for (int mt = 0; mt < 4; mt++)
#pragma unroll
                for (int nt = 0; nt < 4; nt++) {
                    mma_f16(acc[mt][nt], ah[mt], bh[nt]);
                    mma_f16(acc[mt][nt], al[mt], bh[nt]);
                }
        }
        __syncthreads();
    }

    // ---- epilogue ----
    const int g = lane >> 2;
    const int tg = lane & 3;
#pragma unroll
    for (int mt = 0; mt < 4; mt++) {
        int row = bm + warp_m * 64 + mt * 16 + g;
#pragma unroll
        for (int nt = 0; nt < 4; nt++) {
            int col = bn + warp_n * 32 + nt * 8 + tg * 2;
            float bx = bias[col], by = bias[col + 1];
            float v00 = acc[mt][nt][0] + bx, v01 = acc[mt][nt][1] + by;
            float v10 = acc[mt][nt][2] + bx, v11 = acc[mt][nt][3] + by;
            if (fin) {
                float2 a0 = {v00, v01}, a1 = {v10, v11};
                *(float2*)&Cext[(size_t)row * EMB + col] = a0;
                *(float2*)&Cext[(size_t)(row + 8) * EMB + col] = a1;
            } else if (z == 0) {   // Q: split hi/lo
                __half h00 = __float2half(v00), h01 = __float2half(v01);
                __half h10 = __float2half(v10), h11 = __float2half(v11);
                *(uint32_t*)&g_qhi[(size_t)row * EMB + col] = pack_h(h00, h01);
                *(uint32_t*)&g_qhi[(size_t)(row + 8) * EMB + col] = pack_h(h10, h11);
                *(uint32_t*)&g_qlo[(size_t)row * EMB + col] =
                    pack_h(__float2half(v00 - __half2float(h00)),
                           __float2half(v01 - __half2float(h01)));
                *(uint32_t*)&g_qlo[(size_t)(row + 8) * EMB + col] =
                    pack_h(__float2half(v10 - __half2float(h10)),
                           __float2half(v11 - __half2float(h11)));
            } else {               // K or V: plain fp16
                __half* dst = (z == 1) ? g_kh : g_vh;
                *(uint32_t*)&dst[(size_t)row * EMB + col] =
                    pack_h(__float2half(v00), __float2half(v01));
                *(uint32_t*)&dst[(size_t)(row + 8) * EMB + col] =
                    pack_h(__float2half(v10), __float2half(v11));
            }
        }
    }
}

// ---------------------------------------------------------------------------
// HMMA banded flash attention, fp16 2-pass. One CTA per (b,h,64-q tile), 4 warps.
// smem 16KB: Q staging (hi 0..8K, lo 8..16K) -> then K chunk (0..8K), Vt (8..16K)
// ---------------------------------------------------------------------------
__global__ __launch_bounds__(128) void attn_mma()
{
    __shared__ __align__(1024) char smem_buf[16384];
    const uint32_t bK = smem_u32(smem_buf);          // K chunk / Q-hi staging
    const uint32_t bV = bK + 8192;                   // Vt chunk / Q-lo staging
    char* sV = smem_buf + 8192;

    const int tid = threadIdx.x;
    const int lane = tid & 31;
    const int wid = tid >> 5;
    const int q0 = blockIdx.x * 64;
    const int h = blockIdx.y;
    const int b = blockIdx.z;

    const int lr = lane & 15;
    const int lh = lane >> 4;
    const int l7 = lane & 7;
    const int g = lane >> 2;
    const int tg = lane & 3;

    const size_t tok0 = (size_t)b * SEQ;
    const int colh = h * DHEAD;

    // ---- stage Q (hi+lo) into smem, extract fragments ----
#pragma unroll
    for (int i = 0; i < 8; i++) {
        int t = i >> 2;
        int idx = tid + (i & 3) * 128;
        int rr = idx >> 3, cc = idx & 7;
        const __half* src = (t ? g_qlo : g_qhi) + (tok0 + q0 + rr) * EMB + colh + cc * 8;
        cp16(bK + t * 8192 + rr * 128 + ((cc ^ (rr & 7)) * 16), src);
    }
    CP_COMMIT(); CP_WAIT(0); __syncthreads();

    uint32_t qh[4][4], ql[4][4];
#pragma unroll
    for (int kk = 0; kk < 4; kk++) {
        uint32_t ch = (uint32_t)(((kk * 2) | lh) ^ l7) * 16;
        uint32_t off = (uint32_t)(wid * 16 + lr) * 128 + ch;
        ldm_x4(qh[kk][0], qh[kk][1], qh[kk][2], qh[kk][3], bK + off);
        ldm_x4(ql[kk][0], ql[kk][1], ql[kk][2], ql[kk][3], bK + 8192 + off);
    }
    __syncthreads();

    float oacc[8][4];
#pragma unroll
    for (int j = 0; j < 8; j++)
#pragma unroll
        for (int c = 0; c < 4; c++) oacc[j][c] = 0.f;

    float m0 = -1e30f, m8 = -1e30f, l0 = 0.f, l8 = 0.f;
    const float rs = 0.044194173824159216f;  // 1/sqrt(512)

    const int qg0 = q0 + wid * 16 + g;
    const int qg8 = qg0 + 8;

    int klo_ = q0 - WINDOW; if (klo_ < 0) klo_ = 0;
    int khi_ = q0 + 64 + WINDOW; if (khi_ > SEQ) khi_ = SEQ;

    for (int kc = klo_; kc < khi_; kc += 64) {
        // ---- K chunk (plain fp16) via cp.async ----
#pragma unroll
        for (int i = 0; i < 4; i++) {
            int idx = tid + i * 128;
            int rr = idx >> 3, cc = idx & 7;
            const __half* src = g_kh + (tok0 + kc + rr) * EMB + colh + cc * 8;
            cp16(bK + rr * 128 + ((cc ^ (rr & 7)) * 16), src);
        }
        CP_COMMIT();
        // ---- V chunk: [key][dim] -> Vt[dim][key] (plain fp16) ----
#pragma unroll
        for (int i = 0; i < 4; i++) {
            int idx = tid + i * 128;
            int key = idx & 63, dg = idx >> 6;
            __align__(16) __half e[8];
            *(uint4*)e = *(const uint4*)(g_vh + (tok0 + kc + key) * EMB + colh + dg * 8);
#pragma unroll
            for (int ee = 0; ee < 8; ee++) {
                int d = dg * 8 + ee;
                *(__half*)(sV + d * 128 + (((key >> 3) ^ (d & 7)) * 16) + (key & 7) * 2) = e[ee];
            }
        }
        CP_WAIT(0);
        __syncthreads();

        // ---- S = Q K^T (2-pass: Qh·K + Ql·K) ----
        float sacc[8][4];
#pragma unroll
        for (int j = 0; j < 8; j++)
#pragma unroll
            for (int c = 0; c < 4; c++) sacc[j][c] = 0.f;

#pragma unroll
        for (int kk = 0; kk < 4; kk++) {
            uint32_t ch = (uint32_t)(((kk * 2) | lh) ^ l7) * 16;
            uint32_t bh[8][2];
#pragma unroll
            for (int p = 0; p < 4; p++) {
                uint32_t off = (uint32_t)(p * 16 + lr) * 128 + ch;
                uint32_t r0, r1, r2, r3;
                ldm_x4(r0, r1, r2, r3, bK + off);
                bh[p * 2][0] = r0; bh[p * 2][1] = r2;
                bh[p * 2 + 1][0] = r1; bh[p * 2 + 1][1] = r3;
            }
#pragma unroll
            for (int j = 0; j < 8; j++) {
                mma_f16(sacc[j], qh[kk], bh[j]);
                mma_f16(sacc[j], ql[kk], bh[j]);
            }
        }

        // ---- mask + scale + row max ----
        float tmx0 = -1e30f, tmx8 = -1e30f;
#pragma unroll
        for (int j = 0; j < 8; j++) {
            int kg = kc + j * 8 + tg * 2;
            float s0 = sacc[j][0] * rs, s1 = sacc[j][1] * rs;
            float s2 = sacc[j][2] * rs, s3 = sacc[j][3] * rs;
            if (abs(qg0 - kg) > WINDOW)       s0 = -1e30f;
            if (abs(qg0 - (kg + 1)) > WINDOW) s1 = -1e30f;
            if (abs(qg8 - kg) > WINDOW)       s2 = -1e30f;
            if (abs(qg8 - (kg + 1)) > WINDOW) s3 = -1e30f;
            sacc[j][0] = s0; sacc[j][1] = s1; sacc[j][2] = s2; sacc[j][3] = s3;
            tmx0 = fmaxf(tmx0, fmaxf(s0, s1));
            tmx8 = fmaxf(tmx8, fmaxf(s2, s3));
        }
        tmx0 = fmaxf(tmx0, __shfl_xor_sync(0xffffffffu, tmx0, 1));
        tmx0 = fmaxf(tmx0, __shfl_xor_sync(0xffffffffu, tmx0, 2));
        tmx8 = fmaxf(tmx8, __shfl_xor_sync(0xffffffffu, tmx8, 1));
        tmx8 = fmaxf(tmx8, __shfl_xor_sync(0xffffffffu, tmx8, 2));

        float mn0 = fmaxf(m0, tmx0), mn8 = fmaxf(m8, tmx8);
        float f0 = __expf(m0 - mn0), f8 = __expf(m8 - mn8);

        // ---- exp, split P to fp16 hi/lo, row sums ----
        float ls0 = 0.f, ls8 = 0.f;
        uint32_t phg[8], phg8[8], plg[8], plg8[8];
#pragma unroll
        for (int j = 0; j < 8; j++) {
            float p0 = __expf(sacc[j][0] - mn0);
            float p1 = __expf(sacc[j][1] - mn0);
            float p2 = __expf(sacc[j][2] - mn8);
            float p3 = __expf(sacc[j][3] - mn8);
            ls0 += p0 + p1; ls8 += p2 + p3;
            __half h0 = __float2half(p0), h1 = __float2half(p1);
            __half h2 = __float2half(p2), h3 = __float2half(p3);
            phg[j]  = pack_h(h0, h1);
            phg8[j] = pack_h(h2, h3);
            plg[j]  = pack_h(__float2half(p0 - __half2float(h0)),
                             __float2half(p1 - __half2float(h1)));
            plg8[j] = pack_h(__float2half(p2 - __half2float(h2)),
                             __float2half(p3 - __half2float(h3)));
        }
        ls0 += __shfl_xor_sync(0xffffffffu, ls0, 1);
        ls0 += __shfl_xor_sync(0xffffffffu, ls0, 2);
        ls8 += __shfl_xor_sync(0xffffffffu, ls8, 1);
        ls8 += __shfl_xor_sync(0xffffffffu, ls8, 2);
        l0 = l0 * f0 + ls0;
        l8 = l8 * f8 + ls8;
        m0 = mn0; m8 = mn8;

#pragma unroll
        for (int j = 0; j < 8; j++) {
            oacc[j][0] *= f0; oacc[j][1] *= f0;
            oacc[j][2] *= f8; oacc[j][3] *= f8;
        }

        // ---- O += P V (2-pass: Ph·V + Pl·V) ----
#pragma unroll
        for (int t = 0; t < 4; t++) {
            uint32_t ch = (uint32_t)(((t * 2) | lh) ^ l7) * 16;
            uint32_t vh[8][2];
#pragma unroll
            for (int p = 0; p < 4; p++) {
                uint32_t off = (uint32_t)(p * 16 + lr) * 128 + ch;
                uint32_t r0, r1, r2, r3;
                ldm_x4(r0, r1, r2, r3, bV + off);
                vh[p * 2][0] = r0; vh[p * 2][1] = r2;
                vh[p * 2 + 1][0] = r1; vh[p * 2 + 1][1] = r3;
            }
            uint32_t pa_h[4] = {phg[2 * t], phg8[2 * t], phg[2 * t + 1], phg8[2 * t + 1]};
            uint32_t pa_l[4] = {plg[2 * t], plg8[2 * t], plg[2 * t + 1], plg8[2 * t + 1]};
#pragma unroll
            for (int j = 0; j < 8; j++) {
                mma_f16(oacc[j], pa_h, vh[j]);
                mma_f16(oacc[j], pa_l, vh[j]);
            }
        }
        __syncthreads();
    }

    // ---- epilogue: normalize, split to hi/lo fp16, store ----
    float il0 = 1.f / l0, il8 = 1.f / l8;
    size_t r0base = (tok0 + qg0) * EMB + colh;
    size_t r8base = (tok0 + qg8) * EMB + colh;
#pragma unroll
    for (int j = 0; j < 8; j++) {
        int col = j * 8 + tg * 2;
        float v00 = oacc[j][0] * il0, v01 = oacc[j][1] * il0;
        float v10 = oacc[j][2] * il8, v11 = oacc[j][3] * il8;
        __half h00 = __float2half(v00), h01 = __float2half(v01);
        __half h10 = __float2half(v10), h11 = __float2half(v11);
        *(uint32_t*)&g_ohi[r0base + col] = pack_h(h00, h01);
        *(uint32_t*)&g_ohi[r8base + col] = pack_h(h10, h11);
        *(uint32_t*)&g_olo[r0base + col] =
            pack_h(__float2half(v00 - __half2float(h00)),
                   __float2half(v01 - __half2float(h01)));
        *(uint32_t*)&g_olo[r8base + col] =
            pack_h(__float2half(v10 - __half2float(h10)),
                   __float2half(v11 - __half2float(h11)));
    }
}

// ---------------------------------------------------------------------------
extern "C" void kernel_launch(void* const* d_in, const int* in_sizes, int n_in,
                              void* d_out, int out_size)
{
    const float* x  = (const float*)d_in[0];
    const float* Wq = (const float*)d_in[1];
    const float* bq = (const float*)d_in[2];
    const float* Wk = (const float*)d_in[3];
    const float* bk = (const float*)d_in[4];
    const float* Wv = (const float*)d_in[5];
    const float* bv = (const float*)d_in[6];
    const float* Wo = (const float*)d_in[7];
    const float* bo = (const float*)d_in[8];
    float* out = (float*)d_out;

    cudaFuncSetAttribute(gemm_mma, cudaFuncAttributeMaxDynamicSharedMemorySize, GEMM_SMEM);

    int n4 = MTOT * EMB / 4;
    int w4 = EMB * EMB / 4;
    conv_x<<<(n4 + 255) / 256, 256>>>(x, n4);
    conv_w<<<dim3((w4 + 255) / 256, 4), 256>>>(Wq, Wk, Wv, Wo, w4);

    gemm_mma<<<dim3(MTOT / 128, EMB / 128, 3), 256, GEMM_SMEM>>>(bq, bk, bv, nullptr, 0);

    attn_mma<<<dim3(SEQ / 64, NHEAD, BATCH), 128>>>();

    gemm_mma<<<dim3(MTOT / 128, EMB / 128, 1), 256, GEMM_SMEM>>>(bo, nullptr, nullptr, out, 1);
}

// round 8
// speedup vs baseline: 4.0887x; 1.2369x over previous
#include <cuda_runtime.h>
#include <cuda_fp16.h>
#include <math.h>
#include <stdint.h>

#define EMB 512
#define NHEAD 8
#define DHEAD 64
#define SEQ 4096
#define BATCH 2
#define WINDOW 128
#define MTOT (BATCH * SEQ)   // 8192

// fp16 operands ([token][EMB] layout)
__device__ __half g_xhi[(size_t)MTOT * EMB];
__device__ __half g_xlo[(size_t)MTOT * EMB];
__device__ __half g_qh [(size_t)MTOT * EMB];
__device__ __half g_kh [(size_t)MTOT * EMB];
__device__ __half g_vh [(size_t)MTOT * EMB];
__device__ __half g_ohi[(size_t)MTOT * EMB];
__device__ __half g_olo[(size_t)MTOT * EMB];
__device__ __half g_w[4][EMB * EMB];          // plain fp16 weights

// ---------------------------------------------------------------------------
// helpers (base sm_103 ISA: cp.async + ldmatrix + mma.sync)
// ---------------------------------------------------------------------------
static __device__ __forceinline__ uint32_t smem_u32(const void* p) {
    uint32_t a;
    asm("{ .reg .u64 t; cvta.to.shared.u64 t, %1; cvt.u32.u64 %0, t; }"
        : "=r"(a) : "l"(p));
    return a;
}
static __device__ __forceinline__ void cp16(uint32_t dst, const void* src) {
    asm volatile("cp.async.cg.shared.global [%0], [%1], 16;" :: "r"(dst), "l"(src));
}
#define CP_COMMIT() asm volatile("cp.async.commit_group;" ::: "memory")
#define CP_WAIT(n)  asm volatile("cp.async.wait_group %0;" :: "n"(n) : "memory")

static __device__ __forceinline__ void ldm_x4(uint32_t& r0, uint32_t& r1,
                                              uint32_t& r2, uint32_t& r3, uint32_t a) {
    asm volatile("ldmatrix.sync.aligned.m8n8.x4.shared.b16 {%0,%1,%2,%3}, [%4];"
                 : "=r"(r0), "=r"(r1), "=r"(r2), "=r"(r3) : "r"(a));
}
static __device__ __forceinline__ void ldm_x4_t(uint32_t& r0, uint32_t& r1,
                                                uint32_t& r2, uint32_t& r3, uint32_t a) {
    asm volatile("ldmatrix.sync.aligned.m8n8.x4.trans.shared.b16 {%0,%1,%2,%3}, [%4];"
                 : "=r"(r0), "=r"(r1), "=r"(r2), "=r"(r3) : "r"(a));
}
static __device__ __forceinline__ void mma_f16(float* d, const uint32_t* a, const uint32_t* b) {
    asm volatile(
        "mma.sync.aligned.m16n8k16.row.col.f32.f16.f16.f32 "
        "{%0,%1,%2,%3}, {%4,%5,%6,%7}, {%8,%9}, {%0,%1,%2,%3};"
        : "+f"(d[0]), "+f"(d[1]), "+f"(d[2]), "+f"(d[3])
        : "r"(a[0]), "r"(a[1]), "r"(a[2]), "r"(a[3]), "r"(b[0]), "r"(b[1]));
}
static __device__ __forceinline__ uint32_t pack_h(__half a, __half b) {
    __half2 t; t.x = a; t.y = b;
    return *(uint32_t*)&t;
}

// ---------------------------------------------------------------------------
// conversions
// ---------------------------------------------------------------------------
__global__ __launch_bounds__(256) void conv_x(const float* __restrict__ src, int n4)
{
    int i = blockIdx.x * blockDim.x + threadIdx.x;
    if (i >= n4) return;
    float4 v = ((const float4*)src)[i];
    float f[4] = {v.x, v.y, v.z, v.w};
    __align__(8) __half h[4], l[4];
#pragma unroll
    for (int j = 0; j < 4; j++) {
        h[j] = __float2half(f[j]);
        l[j] = __float2half(f[j] - __half2float(h[j]));
    }
    ((uint2*)g_xhi)[i] = *(uint2*)h;
    ((uint2*)g_xlo)[i] = *(uint2*)l;
}

__global__ __launch_bounds__(256) void conv_w(
    const float* __restrict__ w0, const float* __restrict__ w1,
    const float* __restrict__ w2, const float* __restrict__ w3, int n4)
{
    int i = blockIdx.x * blockDim.x + threadIdx.x;
    if (i >= n4) return;
    const float* srcs[4] = {w0, w1, w2, w3};
    const float* src = srcs[blockIdx.y];
    __half* dst = g_w[blockIdx.y];
    float4 v = ((const float4*)src)[i];
    __align__(8) __half h[4];
    h[0] = __float2half(v.x); h[1] = __float2half(v.y);
    h[2] = __float2half(v.z); h[3] = __float2half(v.w);
    ((uint2*)dst)[i] = *(uint2*)h;
}

// ---------------------------------------------------------------------------
// HMMA GEMM: C[m,n] = sum_k A[m,k]*W[n,k] + bias[n],  M=8192, N=K=512
// Single-pass fp16 for Q/K (z=0,1); 2-pass (A=Ah+Al) for V (z=2) and final.
// 128x128 tile, K-chunk 64, double buffer, 8 warps (2Mx4N).
// ---------------------------------------------------------------------------
#define TILE_BYTES 16384            // 128 rows x 128B
#define STAGE_BYTES (3 * TILE_BYTES) // Ah, W, (Al)
#define GEMM_SMEM (2 * STAGE_BYTES)  // 96 KB

static __device__ __forceinline__ void load_stage(
    uint32_t sbase, int buf, int k0, int tid,
    const __half* tAh, const __half* tW, const __half* tAl, int three)
{
    uint32_t stb = sbase + (uint32_t)buf * STAGE_BYTES;
    const __half* t01[2] = {tAh, tW};
#pragma unroll
    for (int i = 0; i < 8; i++) {
        int t = i >> 2;
        int idx = tid + (i & 3) * 256;
        int rr = (idx >> 3) & 127;
        int cc = idx & 7;
        uint32_t dst = stb + t * TILE_BYTES + rr * 128 + ((cc ^ (rr & 7)) * 16);
        cp16(dst, t01[t] + (size_t)rr * EMB + k0 + cc * 8);
    }
    if (three) {
#pragma unroll
        for (int i = 0; i < 4; i++) {
            int idx = tid + i * 256;
            int rr = (idx >> 3) & 127;
            int cc = idx & 7;
            uint32_t dst = stb + 2 * TILE_BYTES + rr * 128 + ((cc ^ (rr & 7)) * 16);
            cp16(dst, tAl + (size_t)rr * EMB + k0 + cc * 8);
        }
    }
    CP_COMMIT();
}

__global__ __launch_bounds__(256, 1) void gemm_mma(
    const float* __restrict__ b0, const float* __restrict__ b1,
    const float* __restrict__ b2, float* __restrict__ Cext, int fin)
{
    extern __shared__ __align__(1024) char dsm[];
    const uint32_t sbase = smem_u32(dsm);

    const int z = blockIdx.z;
    const int two = fin ? 1 : (z == 2);
    const float* bias = fin ? b0 : (z == 0 ? b0 : (z == 1 ? b1 : b2));
    const __half* Ah = fin ? g_ohi : g_xhi;
    const __half* Al = fin ? g_olo : g_xlo;
    const __half* Bw = g_w[fin ? 3 : z];

    const int tid = threadIdx.x;
    const int lane = tid & 31;
    const int wid = tid >> 5;
    const int warp_m = wid >> 2;
    const int warp_n = wid & 3;
    const int bm = blockIdx.x * 128;
    const int bn = blockIdx.y * 128;

    const int lr = lane & 15;
    const int lh = lane >> 4;
    const int l7 = lane & 7;

    float acc[4][4][4];
#pragma unroll
    for (int mt = 0; mt < 4; mt++)
#pragma unroll
        for (int nt = 0; nt < 4; nt++)
#pragma unroll
            for (int j = 0; j < 4; j++) acc[mt][nt][j] = 0.f;

    const __half* tA_h = Ah + (size_t)bm * EMB;
    const __half* tA_l = Al + (size_t)bm * EMB;
    const __half* tB   = Bw + (size_t)bn * EMB;

    load_stage(sbase, 0, 0, tid, tA_h, tB, tA_l, two);

    const uint32_t arow_off = (uint32_t)(warp_m * 64 + lr) * 128;
    const uint32_t brow_off = (uint32_t)(warp_n * 32 + lr) * 128;

    for (int c = 0; c < 8; ++c) {
        const int buf = c & 1;
        if (c + 1 < 8) {
            load_stage(sbase, buf ^ 1, (c + 1) * 64, tid, tA_h, tB, tA_l, two);
            CP_WAIT(1);
        } else {
            CP_WAIT(0);
        }
        __syncthreads();

        const uint32_t sAh = sbase + buf * STAGE_BYTES;
        const uint32_t sB  = sAh + TILE_BYTES;
        const uint32_t sAl = sAh + 2 * TILE_BYTES;

#pragma unroll
        for (int kk = 0; kk < 4; kk++) {
            const uint32_t ch = (uint32_t)(((kk * 2) | lh) ^ l7) * 16;
            uint32_t ah[4][4], al[4][4], bh[4][2];
#pragma unroll
            for (int mt = 0; mt < 4; mt++) {
                uint32_t off = arow_off + (uint32_t)(mt * 16) * 128 + ch;
                ldm_x4(ah[mt][0], ah[mt][1], ah[mt][2], ah[mt][3], sAh + off);
            }
            if (two) {
#pragma unroll
                for (int mt = 0; mt < 4; mt++) {
                    uint32_t off = arow_off + (uint32_t)(mt * 16) * 128 + ch;
                    ldm_x4(al[mt][0], al[mt][1], al[mt][2], al[mt][3], sAl + off);
                }
            }
#pragma unroll
            for (int p = 0; p < 2; p++) {
                uint32_t off = brow_off + (uint32_t)(p * 16) * 128 + ch;
                uint32_t r0, r1, r2, r3;
                ldm_x4(r0, r1, r2, r3, sB + off);
                bh[p * 2][0] = r0; bh[p * 2][1] = r2;
                bh[p * 2 + 1][0] = r1; bh[p * 2 + 1][1] = r3;
            }
#pragma unroll
            for (int mt = 0; mt < 4; mt++)
#pragma unroll
                for (int nt = 0; nt < 4; nt++) {
                    mma_f16(acc[mt][nt], ah[mt], bh[nt]);
                    if (two) mma_f16(acc[mt][nt], al[mt], bh[nt]);
                }
        }
        __syncthreads();
    }

    // ---- epilogue ----
    const int g = lane >> 2;
    const int tg = lane & 3;
#pragma unroll
    for (int mt = 0; mt < 4; mt++) {
        int row = bm + warp_m * 64 + mt * 16 + g;
#pragma unroll
        for (int nt = 0; nt < 4; nt++) {
            int col = bn + warp_n * 32 + nt * 8 + tg * 2;
            float bx = bias[col], by = bias[col + 1];
            float v00 = acc[mt][nt][0] + bx, v01 = acc[mt][nt][1] + by;
            float v10 = acc[mt][nt][2] + bx, v11 = acc[mt][nt][3] + by;
            if (fin) {
                float2 a0 = {v00, v01}, a1 = {v10, v11};
                *(float2*)&Cext[(size_t)row * EMB + col] = a0;
                *(float2*)&Cext[(size_t)(row + 8) * EMB + col] = a1;
            } else {
                __half* dst = (z == 0) ? g_qh : ((z == 1) ? g_kh : g_vh);
                *(uint32_t*)&dst[(size_t)row * EMB + col] =
                    pack_h(__float2half(v00), __float2half(v01));
                *(uint32_t*)&dst[(size_t)(row + 8) * EMB + col] =
                    pack_h(__float2half(v10), __float2half(v11));
            }
        }
    }
}

// ---------------------------------------------------------------------------
// HMMA banded flash attention, fp16. One CTA per (b,h,64-q tile), 4 warps.
// Q plain fp16 (1-pass S), P hi/lo (2-pass PV), V via cp.async + ldmatrix.trans.
// smem 32KB: 2 x (K tile 8KB + V tile 8KB), double-buffered chunks.
// ---------------------------------------------------------------------------
__global__ __launch_bounds__(128) void attn_mma()
{
    __shared__ __align__(1024) char smem_buf[32768];
    const uint32_t sb0 = smem_u32(smem_buf);

    const int tid = threadIdx.x;
    const int lane = tid & 31;
    const int wid = tid >> 5;
    const int q0 = blockIdx.x * 64;
    const int h = blockIdx.y;
    const int b = blockIdx.z;

    const int lr = lane & 15;
    const int lh = lane >> 4;
    const int l7 = lane & 7;
    const int g = lane >> 2;
    const int tg = lane & 3;

    const size_t tok0 = (size_t)b * SEQ;
    const int colh = h * DHEAD;

    // ---- stage Q into buf0 K-region, extract fragments ----
#pragma unroll
    for (int i = 0; i < 4; i++) {
        int idx = tid + i * 128;
        int rr = idx >> 3, cc = idx & 7;
        cp16(sb0 + rr * 128 + ((cc ^ (rr & 7)) * 16),
             g_qh + (tok0 + q0 + rr) * EMB + colh + cc * 8);
    }
    CP_COMMIT(); CP_WAIT(0); __syncthreads();

    uint32_t qh[4][4];
#pragma unroll
    for (int kk = 0; kk < 4; kk++) {
        uint32_t ch = (uint32_t)(((kk * 2) | lh) ^ l7) * 16;
        uint32_t off = (uint32_t)(wid * 16 + lr) * 128 + ch;
        ldm_x4(qh[kk][0], qh[kk][1], qh[kk][2], qh[kk][3], sb0 + off);
    }
    __syncthreads();

    float oacc[8][4];
#pragma unroll
    for (int j = 0; j < 8; j++)
#pragma unroll
        for (int c = 0; c < 4; c++) oacc[j][c] = 0.f;

    float m0 = -1e30f, m8 = -1e30f, l0 = 0.f, l8 = 0.f;
    const float rs = 0.044194173824159216f;  // 1/sqrt(512)

    const int qg0 = q0 + wid * 16 + g;
    const int qg8 = qg0 + 8;

    int klo_ = q0 - WINDOW; if (klo_ < 0) klo_ = 0;
    int khi_ = q0 + 64 + WINDOW; if (khi_ > SEQ) khi_ = SEQ;
    const int nch = (khi_ - klo_) >> 6;

    // K/V chunk loader: buf region = sb0 + buf*16384; K at +0, V at +8192.
    auto load_kv = [&](int buf, int kc) {
        uint32_t base = sb0 + (uint32_t)buf * 16384;
#pragma unroll
        for (int i = 0; i < 4; i++) {
            int idx = tid + i * 128;
            int rr = idx >> 3, cc = idx & 7;
            uint32_t so = rr * 128 + ((cc ^ (rr & 7)) * 16);
            cp16(base + so, g_kh + (tok0 + kc + rr) * EMB + colh + cc * 8);
            cp16(base + 8192 + so, g_vh + (tok0 + kc + rr) * EMB + colh + cc * 8);
        }
        CP_COMMIT();
    };

    load_kv(0, klo_);

    for (int c = 0; c < nch; c++) {
        const int kc = klo_ + c * 64;
        const int buf = c & 1;
        CP_WAIT(0);
        __syncthreads();
        if (c + 1 < nch) load_kv(buf ^ 1, kc + 64);

        const uint32_t bK = sb0 + (uint32_t)buf * 16384;
        const uint32_t bV = bK + 8192;

        // ---- S = Q K^T (1-pass) ----
        float sacc[8][4];
#pragma unroll
        for (int j = 0; j < 8; j++)
#pragma unroll
            for (int cc = 0; cc < 4; cc++) sacc[j][cc] = 0.f;

#pragma unroll
        for (int kk = 0; kk < 4; kk++) {
            uint32_t ch = (uint32_t)(((kk * 2) | lh) ^ l7) * 16;
            uint32_t bh[8][2];
#pragma unroll
            for (int p = 0; p < 4; p++) {
                uint32_t off = (uint32_t)(p * 16 + lr) * 128 + ch;
                uint32_t r0, r1, r2, r3;
                ldm_x4(r0, r1, r2, r3, bK + off);
                bh[p * 2][0] = r0; bh[p * 2][1] = r2;
                bh[p * 2 + 1][0] = r1; bh[p * 2 + 1][1] = r3;
            }
#pragma unroll
            for (int j = 0; j < 8; j++)
                mma_f16(sacc[j], qh[kk], bh[j]);
        }

        // ---- mask + scale + row max ----
        float tmx0 = -1e30f, tmx8 = -1e30f;
#pragma unroll
        for (int j = 0; j < 8; j++) {
            int kg = kc + j * 8 + tg * 2;
            float s0 = sacc[j][0] * rs, s1 = sacc[j][1] * rs;
            float s2 = sacc[j][2] * rs, s3 = sacc[j][3] * rs;
            if (abs(qg0 - kg) > WINDOW)       s0 = -1e30f;
            if (abs(qg0 - (kg + 1)) > WINDOW) s1 = -1e30f;
            if (abs(qg8 - kg) > WINDOW)       s2 = -1e30f;
            if (abs(qg8 - (kg + 1)) > WINDOW) s3 = -1e30f;
            sacc[j][0] = s0; sacc[j][1] = s1; sacc[j][2] = s2; sacc[j][3] = s3;
            tmx0 = fmaxf(tmx0, fmaxf(s0, s1));
            tmx8 = fmaxf(tmx8, fmaxf(s2, s3));
        }
        tmx0 = fmaxf(tmx0, __shfl_xor_sync(0xffffffffu, tmx0, 1));
        tmx0 = fmaxf(tmx0, __shfl_xor_sync(0xffffffffu, tmx0, 2));
        tmx8 = fmaxf(tmx8, __shfl_xor_sync(0xffffffffu, tmx8, 1));
        tmx8 = fmaxf(tmx8, __shfl_xor_sync(0xffffffffu, tmx8, 2));

        float mn0 = fmaxf(m0, tmx0), mn8 = fmaxf(m8, tmx8);
        float f0 = __expf(m0 - mn0), f8 = __expf(m8 - mn8);

        // ---- exp, split P to fp16 hi/lo, row sums ----
        float ls0 = 0.f, ls8 = 0.f;
        uint32_t phg[8], phg8[8], plg[8], plg8[8];
#pragma unroll
        for (int j = 0; j < 8; j++) {
            float p0 = __expf(sacc[j][0] - mn0);
            float p1 = __expf(sacc[j][1] - mn0);
            float p2 = __expf(sacc[j][2] - mn8);
            float p3 = __expf(sacc[j][3] - mn8);
            ls0 += p0 + p1; ls8 += p2 + p3;
            __half h0 = __float2half(p0), h1 = __float2half(p1);
            __half h2 = __float2half(p2), h3 = __float2half(p3);
            phg[j]  = pack_h(h0, h1);
            phg8[j] = pack_h(h2, h3);
            plg[j]  = pack_h(__float2half(p0 - __half2float(h0)),
                             __float2half(p1 - __half2float(h1)));
            plg8[j] = pack_h(__float2half(p2 - __half2float(h2)),
                             __float2half(p3 - __half2float(h3)));
        }
        ls0 += __shfl_xor_sync(0xffffffffu, ls0, 1);
        ls0 += __shfl_xor_sync(0xffffffffu, ls0, 2);
        ls8 += __shfl_xor_sync(0xffffffffu, ls8, 1);
        ls8 += __shfl_xor_sync(0xffffffffu, ls8, 2);
        l0 = l0 * f0 + ls0;
        l8 = l8 * f8 + ls8;
        m0 = mn0; m8 = mn8;

#pragma unroll
        for (int j = 0; j < 8; j++) {
            oacc[j][0] *= f0; oacc[j][1] *= f0;
            oacc[j][2] *= f8; oacc[j][3] *= f8;
        }

        // ---- O += P V (2-pass over P), V fragments via ldmatrix.trans ----
#pragma unroll
        for (int t = 0; t < 4; t++) {
            // B fragments over (k = keys t*16.., n = dims): trans loads
            uint32_t vh[8][2];
            int row = t * 16 + lr;           // key row for this lane
            uint32_t rbase = bV + (uint32_t)row * 128;
            uint32_t rsw = (uint32_t)(row & 7);
#pragma unroll
            for (int pp = 0; pp < 4; pp++) {
                uint32_t d = (uint32_t)(pp * 2) + (uint32_t)lh;  // dim group (16B)
                uint32_t addr = rbase + ((d ^ rsw) * 16);
                uint32_t r0, r1, r2, r3;
                ldm_x4_t(r0, r1, r2, r3, addr);
                vh[pp * 2][0] = r0;     vh[pp * 2][1] = r1;
                vh[pp * 2 + 1][0] = r2; vh[pp * 2 + 1][1] = r3;
            }
            uint32_t pa_h[4] = {phg[2 * t], phg8[2 * t], phg[2 * t + 1], phg8[2 * t + 1]};
            uint32_t pa_l[4] = {plg[2 * t], plg8[2 * t], plg[2 * t + 1], plg8[2 * t + 1]};
#pragma unroll
            for (int j = 0; j < 8; j++) {
                mma_f16(oacc[j], pa_h, vh[j]);
                mma_f16(oacc[j], pa_l, vh[j]);
            }
        }
    }

    // ---- epilogue: normalize, split to hi/lo fp16, store ----
    float il0 = 1.f / l0, il8 = 1.f / l8;
    size_t r0base = (tok0 + qg0) * EMB + colh;
    size_t r8base = (tok0 + qg8) * EMB + colh;
#pragma unroll
    for (int j = 0; j < 8; j++) {
        int col = j * 8 + tg * 2;
        float v00 = oacc[j][0] * il0, v01 = oacc[j][1] * il0;
        float v10 = oacc[j][2] * il8, v11 = oacc[j][3] * il8;
        __half h00 = __float2half(v00), h01 = __float2half(v01);
        __half h10 = __float2half(v10), h11 = __float2half(v11);
        *(uint32_t*)&g_ohi[r0base + col] = pack_h(h00, h01);
        *(uint32_t*)&g_ohi[r8base + col] = pack_h(h10, h11);
        *(uint32_t*)&g_olo[r0base + col] =
            pack_h(__float2half(v00 - __half2float(h00)),
                   __float2half(v01 - __half2float(h01)));
        *(uint32_t*)&g_olo[r8base + col] =
            pack_h(__float2half(v10 - __half2float(h10)),
                   __float2half(v11 - __half2float(h11)));
    }
}

// ---------------------------------------------------------------------------
extern "C" void kernel_launch(void* const* d_in, const int* in_sizes, int n_in,
                              void* d_out, int out_size)
{
    const float* x  = (const float*)d_in[0];
    const float* Wq = (const float*)d_in[1];
    const float* bq = (const float*)d_in[2];
    const float* Wk = (const float*)d_in[3];
    const float* bk = (const float*)d_in[4];
    const float* Wv = (const float*)d_in[5];
    const float* bv = (const float*)d_in[6];
    const float* Wo = (const float*)d_in[7];
    const float* bo = (const float*)d_in[8];
    float* out = (float*)d_out;

    cudaFuncSetAttribute(gemm_mma, cudaFuncAttributeMaxDynamicSharedMemorySize, GEMM_SMEM);

    int n4 = MTOT * EMB / 4;
    int w4 = EMB * EMB / 4;
    conv_x<<<(n4 + 255) / 256, 256>>>(x, n4);
    conv_w<<<dim3((w4 + 255) / 256, 4), 256>>>(Wq, Wk, Wv, Wo, w4);

    gemm_mma<<<dim3(MTOT / 128, EMB / 128, 3), 256, GEMM_SMEM>>>(bq, bk, bv, nullptr, 0);

    attn_mma<<<dim3(SEQ / 64, NHEAD, BATCH), 128>>>();

    gemm_mma<<<dim3(MTOT / 128, EMB / 128, 1), 256, GEMM_SMEM>>>(bo, nullptr, nullptr, out, 1);
}

// round 9
// speedup vs baseline: 6.0028x; 1.4682x over previous
#include <cuda_runtime.h>
#include <cuda_fp16.h>
#include <math.h>
#include <stdint.h>

#define EMB 512
#define NHEAD 8
#define DHEAD 64
#define SEQ 4096
#define BATCH 2
#define WINDOW 128
#define MTOT (BATCH * SEQ)   // 8192

// fp16 operands ([token][EMB] layout)
__device__ __half g_xh[(size_t)MTOT * EMB];
__device__ __half g_qh[(size_t)MTOT * EMB];
__device__ __half g_kh[(size_t)MTOT * EMB];
__device__ __half g_vh[(size_t)MTOT * EMB];
__device__ __half g_oh[(size_t)MTOT * EMB];
__device__ __half g_w[4][EMB * EMB];          // fp16 weights

// ---------------------------------------------------------------------------
// helpers (base sm_103 ISA: cp.async + ldmatrix + mma.sync)
// ---------------------------------------------------------------------------
static __device__ __forceinline__ uint32_t smem_u32(const void* p) {
    uint32_t a;
    asm("{ .reg .u64 t; cvta.to.shared.u64 t, %1; cvt.u32.u64 %0, t; }"
        : "=r"(a) : "l"(p));
    return a;
}
static __device__ __forceinline__ void cp16(uint32_t dst, const void* src) {
    asm volatile("cp.async.cg.shared.global [%0], [%1], 16;" :: "r"(dst), "l"(src));
}
#define CP_COMMIT() asm volatile("cp.async.commit_group;" ::: "memory")
#define CP_WAIT(n)  asm volatile("cp.async.wait_group %0;" :: "n"(n) : "memory")

static __device__ __forceinline__ void ldm_x4(uint32_t& r0, uint32_t& r1,
                                              uint32_t& r2, uint32_t& r3, uint32_t a) {
    asm volatile("ldmatrix.sync.aligned.m8n8.x4.shared.b16 {%0,%1,%2,%3}, [%4];"
                 : "=r"(r0), "=r"(r1), "=r"(r2), "=r"(r3) : "r"(a));
}
static __device__ __forceinline__ void ldm_x4_t(uint32_t& r0, uint32_t& r1,
                                                uint32_t& r2, uint32_t& r3, uint32_t a) {
    asm volatile("ldmatrix.sync.aligned.m8n8.x4.trans.shared.b16 {%0,%1,%2,%3}, [%4];"
                 : "=r"(r0), "=r"(r1), "=r"(r2), "=r"(r3) : "r"(a));
}
static __device__ __forceinline__ void mma_f16(float* d, const uint32_t* a, const uint32_t* b) {
    asm volatile(
        "mma.sync.aligned.m16n8k16.row.col.f32.f16.f16.f32 "
        "{%0,%1,%2,%3}, {%4,%5,%6,%7}, {%8,%9}, {%0,%1,%2,%3};"
        : "+f"(d[0]), "+f"(d[1]), "+f"(d[2]), "+f"(d[3])
        : "r"(a[0]), "r"(a[1]), "r"(a[2]), "r"(a[3]), "r"(b[0]), "r"(b[1]));
}
static __device__ __forceinline__ uint32_t pack_h(__half a, __half b) {
    __half2 t; t.x = a; t.y = b;
    return *(uint32_t*)&t;
}

// ---------------------------------------------------------------------------
// conversions
// ---------------------------------------------------------------------------
__global__ __launch_bounds__(256) void conv_x(const float* __restrict__ src, int n4)
{
    int i = blockIdx.x * blockDim.x + threadIdx.x;
    if (i >= n4) return;
    float4 v = ((const float4*)src)[i];
    __align__(8) __half h[4];
    h[0] = __float2half(v.x); h[1] = __float2half(v.y);
    h[2] = __float2half(v.z); h[3] = __float2half(v.w);
    ((uint2*)g_xh)[i] = *(uint2*)h;
}

__global__ __launch_bounds__(256) void conv_w(
    const float* __restrict__ w0, const float* __restrict__ w1,
    const float* __restrict__ w2, const float* __restrict__ w3, int n4)
{
    int i = blockIdx.x * blockDim.x + threadIdx.x;
    if (i >= n4) return;
    const float* srcs[4] = {w0, w1, w2, w3};
    const float* src = srcs[blockIdx.y];
    __half* dst = g_w[blockIdx.y];
    float4 v = ((const float4*)src)[i];
    __align__(8) __half h[4];
    h[0] = __float2half(v.x); h[1] = __float2half(v.y);
    h[2] = __float2half(v.z); h[3] = __float2half(v.w);
    ((uint2*)dst)[i] = *(uint2*)h;
}

// ---------------------------------------------------------------------------
// HMMA GEMM: C[m,n] = sum_k A[m,k]*W[n,k] + bias[n],  M=8192, N=K=512
// Single-pass fp16, fp32 accum. 128x128 tile, K-chunk 64, double buffer,
// 8 warps (2Mx4N). QKV fused: grid (64,4,3); final: grid (64,4,1), fin=1.
// ---------------------------------------------------------------------------
#define TILE_BYTES 16384             // 128 rows x 128B
#define STAGE_BYTES (2 * TILE_BYTES) // A, W
#define GEMM_SMEM (2 * STAGE_BYTES)  // 64 KB

static __device__ __forceinline__ void load_stage(
    uint32_t sbase, int buf, int k0, int tid,
    const __half* tA, const __half* tW)
{
    uint32_t stb = sbase + (uint32_t)buf * STAGE_BYTES;
    const __half* t01[2] = {tA, tW};
#pragma unroll
    for (int i = 0; i < 8; i++) {
        int t = i >> 2;
        int idx = tid + (i & 3) * 256;
        int rr = (idx >> 3) & 127;
        int cc = idx & 7;
        uint32_t dst = stb + t * TILE_BYTES + rr * 128 + ((cc ^ (rr & 7)) * 16);
        cp16(dst, t01[t] + (size_t)rr * EMB + k0 + cc * 8);
    }
    CP_COMMIT();
}

__global__ __launch_bounds__(256, 1) void gemm_mma(
    const float* __restrict__ b0, const float* __restrict__ b1,
    const float* __restrict__ b2, float* __restrict__ Cext, int fin)
{
    extern __shared__ __align__(1024) char dsm[];
    const uint32_t sbase = smem_u32(dsm);

    const int z = blockIdx.z;
    const float* bias = fin ? b0 : (z == 0 ? b0 : (z == 1 ? b1 : b2));
    const __half* Aa = fin ? g_oh : g_xh;
    const __half* Bw = g_w[fin ? 3 : z];

    const int tid = threadIdx.x;
    const int lane = tid & 31;
    const int wid = tid >> 5;
    const int warp_m = wid >> 2;
    const int warp_n = wid & 3;
    const int bm = blockIdx.x * 128;
    const int bn = blockIdx.y * 128;

    const int lr = lane & 15;
    const int lh = lane >> 4;
    const int l7 = lane & 7;

    float acc[4][4][4];
#pragma unroll
    for (int mt = 0; mt < 4; mt++)
#pragma unroll
        for (int nt = 0; nt < 4; nt++)
#pragma unroll
            for (int j = 0; j < 4; j++) acc[mt][nt][j] = 0.f;

    const __half* tA = Aa + (size_t)bm * EMB;
    const __half* tB = Bw + (size_t)bn * EMB;

    load_stage(sbase, 0, 0, tid, tA, tB);

    const uint32_t arow_off = (uint32_t)(warp_m * 64 + lr) * 128;
    const uint32_t brow_off = (uint32_t)(warp_n * 32 + lr) * 128;

    for (int c = 0; c < 8; ++c) {
        const int buf = c & 1;
        if (c + 1 < 8) {
            load_stage(sbase, buf ^ 1, (c + 1) * 64, tid, tA, tB);
            CP_WAIT(1);
        } else {
            CP_WAIT(0);
        }
        __syncthreads();

        const uint32_t sA = sbase + buf * STAGE_BYTES;
        const uint32_t sB = sA + TILE_BYTES;

#pragma unroll
        for (int kk = 0; kk < 4; kk++) {
            const uint32_t ch = (uint32_t)(((kk * 2) | lh) ^ l7) * 16;
            uint32_t ah[4][4], bh[4][2];
#pragma unroll
            for (int mt = 0; mt < 4; mt++) {
                uint32_t off = arow_off + (uint32_t)(mt * 16) * 128 + ch;
                ldm_x4(ah[mt][0], ah[mt][1], ah[mt][2], ah[mt][3], sA + off);
            }
#pragma unroll
            for (int p = 0; p < 2; p++) {
                uint32_t off = brow_off + (uint32_t)(p * 16) * 128 + ch;
                uint32_t r0, r1, r2, r3;
                ldm_x4(r0, r1, r2, r3, sB + off);
                bh[p * 2][0] = r0; bh[p * 2][1] = r2;
                bh[p * 2 + 1][0] = r1; bh[p * 2 + 1][1] = r3;
            }
#pragma unroll
            for (int mt = 0; mt < 4; mt++)
#pragma unroll
                for (int nt = 0; nt < 4; nt++)
                    mma_f16(acc[mt][nt], ah[mt], bh[nt]);
        }
        __syncthreads();
    }

    // ---- epilogue ----
    const int g = lane >> 2;
    const int tg = lane & 3;
#pragma unroll
    for (int mt = 0; mt < 4; mt++) {
        int row = bm + warp_m * 64 + mt * 16 + g;
#pragma unroll
        for (int nt = 0; nt < 4; nt++) {
            int col = bn + warp_n * 32 + nt * 8 + tg * 2;
            float bx = bias[col], by = bias[col + 1];
            float v00 = acc[mt][nt][0] + bx, v01 = acc[mt][nt][1] + by;
            float v10 = acc[mt][nt][2] + bx, v11 = acc[mt][nt][3] + by;
            if (fin) {
                float2 a0 = {v00, v01}, a1 = {v10, v11};
                *(float2*)&Cext[(size_t)row * EMB + col] = a0;
                *(float2*)&Cext[(size_t)(row + 8) * EMB + col] = a1;
            } else {
                __half* dst = (z == 0) ? g_qh : ((z == 1) ? g_kh : g_vh);
                *(uint32_t*)&dst[(size_t)row * EMB + col] =
                    pack_h(__float2half(v00), __float2half(v01));
                *(uint32_t*)&dst[(size_t)(row + 8) * EMB + col] =
                    pack_h(__float2half(v10), __float2half(v11));
            }
        }
    }
}

// ---------------------------------------------------------------------------
// HMMA banded flash attention, single-pass fp16. One CTA per (b,h,64-q tile),
// 4 warps. V via cp.async + ldmatrix.trans. smem 32KB double-buffered K/V.
// ---------------------------------------------------------------------------
__global__ __launch_bounds__(128) void attn_mma()
{
    __shared__ __align__(1024) char smem_buf[32768];
    const uint32_t sb0 = smem_u32(smem_buf);

    const int tid = threadIdx.x;
    const int lane = tid & 31;
    const int wid = tid >> 5;
    const int q0 = blockIdx.x * 64;
    const int h = blockIdx.y;
    const int b = blockIdx.z;

    const int lr = lane & 15;
    const int lh = lane >> 4;
    const int l7 = lane & 7;
    const int g = lane >> 2;
    const int tg = lane & 3;

    const size_t tok0 = (size_t)b * SEQ;
    const int colh = h * DHEAD;

    // ---- stage Q into buf0 K-region, extract fragments ----
#pragma unroll
    for (int i = 0; i < 4; i++) {
        int idx = tid + i * 128;
        int rr = idx >> 3, cc = idx & 7;
        cp16(sb0 + rr * 128 + ((cc ^ (rr & 7)) * 16),
             g_qh + (tok0 + q0 + rr) * EMB + colh + cc * 8);
    }
    CP_COMMIT(); CP_WAIT(0); __syncthreads();

    uint32_t qh[4][4];
#pragma unroll
    for (int kk = 0; kk < 4; kk++) {
        uint32_t ch = (uint32_t)(((kk * 2) | lh) ^ l7) * 16;
        uint32_t off = (uint32_t)(wid * 16 + lr) * 128 + ch;
        ldm_x4(qh[kk][0], qh[kk][1], qh[kk][2], qh[kk][3], sb0 + off);
    }
    __syncthreads();

    float oacc[8][4];
#pragma unroll
    for (int j = 0; j < 8; j++)
#pragma unroll
        for (int c = 0; c < 4; c++) oacc[j][c] = 0.f;

    float m0 = -1e30f, m8 = -1e30f, l0 = 0.f, l8 = 0.f;
    const float rs = 0.044194173824159216f;  // 1/sqrt(512)

    const int qg0 = q0 + wid * 16 + g;
    const int qg8 = qg0 + 8;

    int klo_ = q0 - WINDOW; if (klo_ < 0) klo_ = 0;
    int khi_ = q0 + 64 + WINDOW; if (khi_ > SEQ) khi_ = SEQ;
    const int nch = (khi_ - klo_) >> 6;

    auto load_kv = [&](int buf, int kc) {
        uint32_t base = sb0 + (uint32_t)buf * 16384;
#pragma unroll
        for (int i = 0; i < 4; i++) {
            int idx = tid + i * 128;
            int rr = idx >> 3, cc = idx & 7;
            uint32_t so = rr * 128 + ((cc ^ (rr & 7)) * 16);
            cp16(base + so, g_kh + (tok0 + kc + rr) * EMB + colh + cc * 8);
            cp16(base + 8192 + so, g_vh + (tok0 + kc + rr) * EMB + colh + cc * 8);
        }
        CP_COMMIT();
    };

    load_kv(0, klo_);

    for (int c = 0; c < nch; c++) {
        const int kc = klo_ + c * 64;
        const int buf = c & 1;
        CP_WAIT(0);
        __syncthreads();
        if (c + 1 < nch) load_kv(buf ^ 1, kc + 64);

        const uint32_t bK = sb0 + (uint32_t)buf * 16384;
        const uint32_t bV = bK + 8192;

        // ---- S = Q K^T ----
        float sacc[8][4];
#pragma unroll
        for (int j = 0; j < 8; j++)
#pragma unroll
            for (int cc = 0; cc < 4; cc++) sacc[j][cc] = 0.f;

#pragma unroll
        for (int kk = 0; kk < 4; kk++) {
            uint32_t ch = (uint32_t)(((kk * 2) | lh) ^ l7) * 16;
            uint32_t bh[8][2];
#pragma unroll
            for (int p = 0; p < 4; p++) {
                uint32_t off = (uint32_t)(p * 16 + lr) * 128 + ch;
                uint32_t r0, r1, r2, r3;
                ldm_x4(r0, r1, r2, r3, bK + off);
                bh[p * 2][0] = r0; bh[p * 2][1] = r2;
                bh[p * 2 + 1][0] = r1; bh[p * 2 + 1][1] = r3;
            }
#pragma unroll
            for (int j = 0; j < 8; j++)
                mma_f16(sacc[j], qh[kk], bh[j]);
        }

        // ---- mask + scale + row max ----
        float tmx0 = -1e30f, tmx8 = -1e30f;
#pragma unroll
        for (int j = 0; j < 8; j++) {
            int kg = kc + j * 8 + tg * 2;
            float s0 = sacc[j][0] * rs, s1 = sacc[j][1] * rs;
            float s2 = sacc[j][2] * rs, s3 = sacc[j][3] * rs;
            if (abs(qg0 - kg) > WINDOW)       s0 = -1e30f;
            if (abs(qg0 - (kg + 1)) > WINDOW) s1 = -1e30f;
            if (abs(qg8 - kg) > WINDOW)       s2 = -1e30f;
            if (abs(qg8 - (kg + 1)) > WINDOW) s3 = -1e30f;
            sacc[j][0] = s0; sacc[j][1] = s1; sacc[j][2] = s2; sacc[j][3] = s3;
            tmx0 = fmaxf(tmx0, fmaxf(s0, s1));
            tmx8 = fmaxf(tmx8, fmaxf(s2, s3));
        }
        tmx0 = fmaxf(tmx0, __shfl_xor_sync(0xffffffffu, tmx0, 1));
        tmx0 = fmaxf(tmx0, __shfl_xor_sync(0xffffffffu, tmx0, 2));
        tmx8 = fmaxf(tmx8, __shfl_xor_sync(0xffffffffu, tmx8, 1));
        tmx8 = fmaxf(tmx8, __shfl_xor_sync(0xffffffffu, tmx8, 2));

        float mn0 = fmaxf(m0, tmx0), mn8 = fmaxf(m8, tmx8);
        float f0 = __expf(m0 - mn0), f8 = __expf(m8 - mn8);

        // ---- exp, pack P to fp16, row sums ----
        float ls0 = 0.f, ls8 = 0.f;
        uint32_t phg[8], phg8[8];
#pragma unroll
        for (int j = 0; j < 8; j++) {
            float p0 = __expf(sacc[j][0] - mn0);
            float p1 = __expf(sacc[j][1] - mn0);
            float p2 = __expf(sacc[j][2] - mn8);
            float p3 = __expf(sacc[j][3] - mn8);
            ls0 += p0 + p1; ls8 += p2 + p3;
            phg[j]  = pack_h(__float2half(p0), __float2half(p1));
            phg8[j] = pack_h(__float2half(p2), __float2half(p3));
        }
        ls0 += __shfl_xor_sync(0xffffffffu, ls0, 1);
        ls0 += __shfl_xor_sync(0xffffffffu, ls0, 2);
        ls8 += __shfl_xor_sync(0xffffffffu, ls8, 1);
        ls8 += __shfl_xor_sync(0xffffffffu, ls8, 2);
        l0 = l0 * f0 + ls0;
        l8 = l8 * f8 + ls8;
        m0 = mn0; m8 = mn8;

#pragma unroll
        for (int j = 0; j < 8; j++) {
            oacc[j][0] *= f0; oacc[j][1] *= f0;
            oacc[j][2] *= f8; oacc[j][3] *= f8;
        }

        // ---- O += P V, V fragments via ldmatrix.trans ----
#pragma unroll
        for (int t = 0; t < 4; t++) {
            uint32_t vh[8][2];
            int row = t * 16 + lr;           // key row for this lane
            uint32_t rbase = bV + (uint32_t)row * 128;
            uint32_t rsw = (uint32_t)(row & 7);
#pragma unroll
            for (int pp = 0; pp < 4; pp++) {
                uint32_t d = (uint32_t)(pp * 2) + (uint32_t)lh;  // dim group (16B)
                uint32_t addr = rbase + ((d ^ rsw) * 16);
                uint32_t r0, r1, r2, r3;
                ldm_x4_t(r0, r1, r2, r3, addr);
                vh[pp * 2][0] = r0;     vh[pp * 2][1] = r1;
                vh[pp * 2 + 1][0] = r2; vh[pp * 2 + 1][1] = r3;
            }
            uint32_t pa_h[4] = {phg[2 * t], phg8[2 * t], phg[2 * t + 1], phg8[2 * t + 1]};
#pragma unroll
            for (int j = 0; j < 8; j++)
                mma_f16(oacc[j], pa_h, vh[j]);
        }
    }

    // ---- epilogue: normalize, store plain fp16 ----
    float il0 = 1.f / l0, il8 = 1.f / l8;
    size_t r0base = (tok0 + qg0) * EMB + colh;
    size_t r8base = (tok0 + qg8) * EMB + colh;
#pragma unroll
    for (int j = 0; j < 8; j++) {
        int col = j * 8 + tg * 2;
        *(uint32_t*)&g_oh[r0base + col] =
            pack_h(__float2half(oacc[j][0] * il0), __float2half(oacc[j][1] * il0));
        *(uint32_t*)&g_oh[r8base + col] =
            pack_h(__float2half(oacc[j][2] * il8), __float2half(oacc[j][3] * il8));
    }
}

// ---------------------------------------------------------------------------
extern "C" void kernel_launch(void* const* d_in, const int* in_sizes, int n_in,
                              void* d_out, int out_size)
{
    const float* x  = (const float*)d_in[0];
    const float* Wq = (const float*)d_in[1];
    const float* bq = (const float*)d_in[2];
    const float* Wk = (const float*)d_in[3];
    const float* bk = (const float*)d_in[4];
    const float* Wv = (const float*)d_in[5];
    const float* bv = (const float*)d_in[6];
    const float* Wo = (const float*)d_in[7];
    const float* bo = (const float*)d_in[8];
    float* out = (float*)d_out;

    cudaFuncSetAttribute(gemm_mma, cudaFuncAttributeMaxDynamicSharedMemorySize, GEMM_SMEM);

    int n4 = MTOT * EMB / 4;
    int w4 = EMB * EMB / 4;
    conv_x<<<(n4 + 255) / 256, 256>>>(x, n4);
    conv_w<<<dim3((w4 + 255) / 256, 4), 256>>>(Wq, Wk, Wv, Wo, w4);

    gemm_mma<<<dim3(MTOT / 128, EMB / 128, 3), 256, GEMM_SMEM>>>(bq, bk, bv, nullptr, 0);

    attn_mma<<<dim3(SEQ / 64, NHEAD, BATCH), 128>>>();

    gemm_mma<<<dim3(MTOT / 128, EMB / 128, 1), 256, GEMM_SMEM>>>(bo, nullptr, nullptr, out, 1);
}

// round 10
// speedup vs baseline: 6.7284x; 1.1209x over previous
#include <cuda_runtime.h>
#include <cuda_fp16.h>
#include <math.h>
#include <stdint.h>

#define EMB 512
#define NHEAD 8
#define DHEAD 64
#define SEQ 4096
#define BATCH 2
#define WINDOW 128
#define MTOT (BATCH * SEQ)   // 8192

// fp16 operands ([token][EMB] layout)
__device__ __half g_xh[(size_t)MTOT * EMB];
__device__ __half g_qh[(size_t)MTOT * EMB];   // pre-scaled by 1/sqrt(512)
__device__ __half g_kh[(size_t)MTOT * EMB];
__device__ __half g_vh[(size_t)MTOT * EMB];
__device__ __half g_oh[(size_t)MTOT * EMB];
__device__ __half g_w[4][EMB * EMB];          // fp16 weights

// ---------------------------------------------------------------------------
// helpers (base sm_103 ISA: cp.async + ldmatrix + mma.sync)
// ---------------------------------------------------------------------------
static __device__ __forceinline__ uint32_t smem_u32(const void* p) {
    uint32_t a;
    asm("{ .reg .u64 t; cvta.to.shared.u64 t, %1; cvt.u32.u64 %0, t; }"
        : "=r"(a) : "l"(p));
    return a;
}
static __device__ __forceinline__ void cp16(uint32_t dst, const void* src) {
    asm volatile("cp.async.cg.shared.global [%0], [%1], 16;" :: "r"(dst), "l"(src));
}
#define CP_COMMIT() asm volatile("cp.async.commit_group;" ::: "memory")
#define CP_WAIT(n)  asm volatile("cp.async.wait_group %0;" :: "n"(n) : "memory")

static __device__ __forceinline__ void ldm_x4(uint32_t& r0, uint32_t& r1,
                                              uint32_t& r2, uint32_t& r3, uint32_t a) {
    asm volatile("ldmatrix.sync.aligned.m8n8.x4.shared.b16 {%0,%1,%2,%3}, [%4];"
                 : "=r"(r0), "=r"(r1), "=r"(r2), "=r"(r3) : "r"(a));
}
static __device__ __forceinline__ void ldm_x4_t(uint32_t& r0, uint32_t& r1,
                                                uint32_t& r2, uint32_t& r3, uint32_t a) {
    asm volatile("ldmatrix.sync.aligned.m8n8.x4.trans.shared.b16 {%0,%1,%2,%3}, [%4];"
                 : "=r"(r0), "=r"(r1), "=r"(r2), "=r"(r3) : "r"(a));
}
static __device__ __forceinline__ void mma_f16(float* d, const uint32_t* a, const uint32_t* b) {
    asm volatile(
        "mma.sync.aligned.m16n8k16.row.col.f32.f16.f16.f32 "
        "{%0,%1,%2,%3}, {%4,%5,%6,%7}, {%8,%9}, {%0,%1,%2,%3};"
        : "+f"(d[0]), "+f"(d[1]), "+f"(d[2]), "+f"(d[3])
        : "r"(a[0]), "r"(a[1]), "r"(a[2]), "r"(a[3]), "r"(b[0]), "r"(b[1]));
}
static __device__ __forceinline__ uint32_t pack_h(__half a, __half b) {
    __half2 t; t.x = a; t.y = b;
    return *(uint32_t*)&t;
}

// ---------------------------------------------------------------------------
// conversions
// ---------------------------------------------------------------------------
__global__ __launch_bounds__(256) void conv_x(const float* __restrict__ src, int n4)
{
    int i = blockIdx.x * blockDim.x + threadIdx.x;
    if (i >= n4) return;
    float4 v = ((const float4*)src)[i];
    __align__(8) __half h[4];
    h[0] = __float2half(v.x); h[1] = __float2half(v.y);
    h[2] = __float2half(v.z); h[3] = __float2half(v.w);
    ((uint2*)g_xh)[i] = *(uint2*)h;
}

__global__ __launch_bounds__(256) void conv_w(
    const float* __restrict__ w0, const float* __restrict__ w1,
    const float* __restrict__ w2, const float* __restrict__ w3, int n4)
{
    int i = blockIdx.x * blockDim.x + threadIdx.x;
    if (i >= n4) return;
    const float* srcs[4] = {w0, w1, w2, w3};
    const float* src = srcs[blockIdx.y];
    __half* dst = g_w[blockIdx.y];
    float4 v = ((const float4*)src)[i];
    __align__(8) __half h[4];
    h[0] = __float2half(v.x); h[1] = __float2half(v.y);
    h[2] = __float2half(v.z); h[3] = __float2half(v.w);
    ((uint2*)dst)[i] = *(uint2*)h;
}

// ---------------------------------------------------------------------------
// HMMA GEMM: C[m,n] = sum_k A[m,k]*W[n,k] + bias[n],  M=8192, N=K=512
// Single-pass fp16, fp32 accum. 128x128 tile, K-chunk 64, double buffer,
// 8 warps (2Mx4N). QKV fused: grid (64,4,3); final: grid (64,4,1), fin=1.
// Q output (z==0) is pre-scaled by 1/sqrt(512).
// ---------------------------------------------------------------------------
#define TILE_BYTES 16384             // 128 rows x 128B
#define STAGE_BYTES (2 * TILE_BYTES) // A, W
#define GEMM_SMEM (2 * STAGE_BYTES)  // 64 KB

static __device__ __forceinline__ void load_stage(
    uint32_t sbase, int buf, int k0, int tid,
    const __half* tA, const __half* tW)
{
    uint32_t stb = sbase + (uint32_t)buf * STAGE_BYTES;
    const __half* t01[2] = {tA, tW};
#pragma unroll
    for (int i = 0; i < 8; i++) {
        int t = i >> 2;
        int idx = tid + (i & 3) * 256;
        int rr = (idx >> 3) & 127;
        int cc = idx & 7;
        uint32_t dst = stb + t * TILE_BYTES + rr * 128 + ((cc ^ (rr & 7)) * 16);
        cp16(dst, t01[t] + (size_t)rr * EMB + k0 + cc * 8);
    }
    CP_COMMIT();
}

__global__ __launch_bounds__(256, 2) void gemm_mma(
    const float* __restrict__ b0, const float* __restrict__ b1,
    const float* __restrict__ b2, float* __restrict__ Cext, int fin)
{
    extern __shared__ __align__(1024) char dsm[];
    const uint32_t sbase = smem_u32(dsm);

    const int z = blockIdx.z;
    const float* bias = fin ? b0 : (z == 0 ? b0 : (z == 1 ? b1 : b2));
    const __half* Aa = fin ? g_oh : g_xh;
    const __half* Bw = g_w[fin ? 3 : z];
    const float oscale = (!fin && z == 0) ? 0.044194173824159216f : 1.0f;

    const int tid = threadIdx.x;
    const int lane = tid & 31;
    const int wid = tid >> 5;
    const int warp_m = wid >> 2;
    const int warp_n = wid & 3;
    const int bm = blockIdx.x * 128;
    const int bn = blockIdx.y * 128;

    const int lr = lane & 15;
    const int lh = lane >> 4;
    const int l7 = lane & 7;

    float acc[4][4][4];
#pragma unroll
    for (int mt = 0; mt < 4; mt++)
#pragma unroll
        for (int nt = 0; nt < 4; nt++)
#pragma unroll
            for (int j = 0; j < 4; j++) acc[mt][nt][j] = 0.f;

    const __half* tA = Aa + (size_t)bm * EMB;
    const __half* tB = Bw + (size_t)bn * EMB;

    load_stage(sbase, 0, 0, tid, tA, tB);

    const uint32_t arow_off = (uint32_t)(warp_m * 64 + lr) * 128;
    const uint32_t brow_off = (uint32_t)(warp_n * 32 + lr) * 128;

    for (int c = 0; c < 8; ++c) {
        const int buf = c & 1;
        if (c + 1 < 8) {
            load_stage(sbase, buf ^ 1, (c + 1) * 64, tid, tA, tB);
            CP_WAIT(1);
        } else {
            CP_WAIT(0);
        }
        __syncthreads();

        const uint32_t sA = sbase + buf * STAGE_BYTES;
        const uint32_t sB = sA + TILE_BYTES;

#pragma unroll
        for (int kk = 0; kk < 4; kk++) {
            const uint32_t ch = (uint32_t)(((kk * 2) | lh) ^ l7) * 16;
            uint32_t ah[4][4], bh[4][2];
#pragma unroll
            for (int mt = 0; mt < 4; mt++) {
                uint32_t off = arow_off + (uint32_t)(mt * 16) * 128 + ch;
                ldm_x4(ah[mt][0], ah[mt][1], ah[mt][2], ah[mt][3], sA + off);
            }
#pragma unroll
            for (int p = 0; p < 2; p++) {
                uint32_t off = brow_off + (uint32_t)(p * 16) * 128 + ch;
                uint32_t r0, r1, r2, r3;
                ldm_x4(r0, r1, r2, r3, sB + off);
                bh[p * 2][0] = r0; bh[p * 2][1] = r2;
                bh[p * 2 + 1][0] = r1; bh[p * 2 + 1][1] = r3;
            }
#pragma unroll
            for (int mt = 0; mt < 4; mt++)
#pragma unroll
                for (int nt = 0; nt < 4; nt++)
                    mma_f16(acc[mt][nt], ah[mt], bh[nt]);
        }
        __syncthreads();
    }

    // ---- epilogue ----
    const int g = lane >> 2;
    const int tg = lane & 3;
#pragma unroll
    for (int mt = 0; mt < 4; mt++) {
        int row = bm + warp_m * 64 + mt * 16 + g;
#pragma unroll
        for (int nt = 0; nt < 4; nt++) {
            int col = bn + warp_n * 32 + nt * 8 + tg * 2;
            float bx = bias[col], by = bias[col + 1];
            float v00 = (acc[mt][nt][0] + bx) * oscale, v01 = (acc[mt][nt][1] + by) * oscale;
            float v10 = (acc[mt][nt][2] + bx) * oscale, v11 = (acc[mt][nt][3] + by) * oscale;
            if (fin) {
                float2 a0 = {v00, v01}, a1 = {v10, v11};
                *(float2*)&Cext[(size_t)row * EMB + col] = a0;
                *(float2*)&Cext[(size_t)(row + 8) * EMB + col] = a1;
            } else {
                __half* dst = (z == 0) ? g_qh : ((z == 1) ? g_kh : g_vh);
                *(uint32_t*)&dst[(size_t)row * EMB + col] =
                    pack_h(__float2half(v00), __float2half(v01));
                *(uint32_t*)&dst[(size_t)(row + 8) * EMB + col] =
                    pack_h(__float2half(v10), __float2half(v11));
            }
        }
    }
}

// ---------------------------------------------------------------------------
// HMMA banded flash attention, single-pass fp16. One CTA per (b,h,64-q tile),
// 4 warps (warp w owns queries q0+16w..q0+16w+15). V via ldmatrix.trans.
// Band structure: only chunks at kc == q0-128 (typ 1) / q0+128 (typ 2) have
// masked pairs; within those, 16-key groups p<wid (typ1) / p>wid (typ2) are
// fully masked -> skip their ldm+MMA in both QK and PV.
// ---------------------------------------------------------------------------
__global__ __launch_bounds__(128) void attn_mma()
{
    __shared__ __align__(1024) char smem_buf[32768];
    const uint32_t sb0 = smem_u32(smem_buf);

    const int tid = threadIdx.x;
    const int lane = tid & 31;
    const int wid = tid >> 5;
    const int q0 = blockIdx.x * 64;
    const int h = blockIdx.y;
    const int b = blockIdx.z;

    const int lr = lane & 15;
    const int lh = lane >> 4;
    const int l7 = lane & 7;
    const int g = lane >> 2;
    const int tg = lane & 3;

    const size_t tok0 = (size_t)b * SEQ;
    const int colh = h * DHEAD;

    // ---- stage Q (pre-scaled) into buf0 K-region, extract fragments ----
#pragma unroll
    for (int i = 0; i < 4; i++) {
        int idx = tid + i * 128;
        int rr = idx >> 3, cc = idx & 7;
        cp16(sb0 + rr * 128 + ((cc ^ (rr & 7)) * 16),
             g_qh + (tok0 + q0 + rr) * EMB + colh + cc * 8);
    }
    CP_COMMIT(); CP_WAIT(0); __syncthreads();

    uint32_t qh[4][4];
#pragma unroll
    for (int kk = 0; kk < 4; kk++) {
        uint32_t ch = (uint32_t)(((kk * 2) | lh) ^ l7) * 16;
        uint32_t off = (uint32_t)(wid * 16 + lr) * 128 + ch;
        ldm_x4(qh[kk][0], qh[kk][1], qh[kk][2], qh[kk][3], sb0 + off);
    }
    __syncthreads();

    float oacc[8][4];
#pragma unroll
    for (int j = 0; j < 8; j++)
#pragma unroll
        for (int c = 0; c < 4; c++) oacc[j][c] = 0.f;

    float m0 = -1e30f, m8 = -1e30f, l0 = 0.f, l8 = 0.f;

    const int qg0 = q0 + wid * 16 + g;
    const int qg8 = qg0 + 8;

    int klo_ = q0 - WINDOW; if (klo_ < 0) klo_ = 0;
    int khi_ = q0 + 64 + WINDOW; if (khi_ > SEQ) khi_ = SEQ;
    const int nch = (khi_ - klo_) >> 6;

    auto load_kv = [&](int buf, int kc) {
        uint32_t base = sb0 + (uint32_t)buf * 16384;
#pragma unroll
        for (int i = 0; i < 4; i++) {
            int idx = tid + i * 128;
            int rr = idx >> 3, cc = idx & 7;
            uint32_t so = rr * 128 + ((cc ^ (rr & 7)) * 16);
            cp16(base + so, g_kh + (tok0 + kc + rr) * EMB + colh + cc * 8);
            cp16(base + 8192 + so, g_vh + (tok0 + kc + rr) * EMB + colh + cc * 8);
        }
        CP_COMMIT();
    };

    load_kv(0, klo_);

    for (int c = 0; c < nch; c++) {
        const int kc = klo_ + c * 64;
        const int buf = c & 1;
        const int typ = (kc == q0 - 128) ? 1 : ((kc == q0 + 128) ? 2 : 0);
        // 16-key group bounds (inclusive) for this warp
        const int plo = (typ == 1) ? wid : 0;
        const int phi = (typ == 2) ? wid : 3;

        CP_WAIT(0);
        __syncthreads();
        if (c + 1 < nch) load_kv(buf ^ 1, kc + 64);

        const uint32_t bK = sb0 + (uint32_t)buf * 16384;
        const uint32_t bV = bK + 8192;

        // ---- S = Q K^T (Q pre-scaled; skip fully-masked key groups) ----
        float sacc[8][4];
#pragma unroll
        for (int j = 0; j < 8; j++)
#pragma unroll
            for (int cc = 0; cc < 4; cc++) sacc[j][cc] = -1e30f;

#pragma unroll
        for (int p = 0; p < 4; p++) {
            if (p < plo || p > phi) continue;    // warp-uniform skip
#pragma unroll
            for (int j = 0; j < 2; j++)
#pragma unroll
                for (int cc = 0; cc < 4; cc++) sacc[p * 2 + j][cc] = 0.f;
#pragma unroll
            for (int kk = 0; kk < 4; kk++) {
                uint32_t ch = (uint32_t)(((kk * 2) | lh) ^ l7) * 16;
                uint32_t off = (uint32_t)(p * 16 + lr) * 128 + ch;
                uint32_t r0, r1, r2, r3;
                ldm_x4(r0, r1, r2, r3, bK + off);
                uint32_t b0[2] = {r0, r2}, b1[2] = {r1, r3};
                mma_f16(sacc[p * 2], qh[kk], b0);
                mma_f16(sacc[p * 2 + 1], qh[kk], b1);
            }
        }

        // ---- mask (boundary chunks only) + row max ----
        if (typ) {
#pragma unroll
            for (int j = 0; j < 8; j++) {
                int kg = kc + j * 8 + tg * 2;
                if (abs(qg0 - kg) > WINDOW)       sacc[j][0] = -1e30f;
                if (abs(qg0 - (kg + 1)) > WINDOW) sacc[j][1] = -1e30f;
                if (abs(qg8 - kg) > WINDOW)       sacc[j][2] = -1e30f;
                if (abs(qg8 - (kg + 1)) > WINDOW) sacc[j][3] = -1e30f;
            }
        }
        float tmx0 = -1e30f, tmx8 = -1e30f;
#pragma unroll
        for (int j = 0; j < 8; j++) {
            tmx0 = fmaxf(tmx0, fmaxf(sacc[j][0], sacc[j][1]));
            tmx8 = fmaxf(tmx8, fmaxf(sacc[j][2], sacc[j][3]));
        }
        tmx0 = fmaxf(tmx0, __shfl_xor_sync(0xffffffffu, tmx0, 1));
        tmx0 = fmaxf(tmx0, __shfl_xor_sync(0xffffffffu, tmx0, 2));
        tmx8 = fmaxf(tmx8, __shfl_xor_sync(0xffffffffu, tmx8, 1));
        tmx8 = fmaxf(tmx8, __shfl_xor_sync(0xffffffffu, tmx8, 2));

        float mn0 = fmaxf(m0, tmx0), mn8 = fmaxf(m8, tmx8);
        float f0 = __expf(m0 - mn0), f8 = __expf(m8 - mn8);

        // ---- exp, pack P to fp16, row sums ----
        float ls0 = 0.f, ls8 = 0.f;
        uint32_t phg[8], phg8[8];
#pragma unroll
        for (int j = 0; j < 8; j++) {
            float p0 = __expf(sacc[j][0] - mn0);
            float p1 = __expf(sacc[j][1] - mn0);
            float p2 = __expf(sacc[j][2] - mn8);
            float p3 = __expf(sacc[j][3] - mn8);
            ls0 += p0 + p1; ls8 += p2 + p3;
            phg[j]  = pack_h(__float2half(p0), __float2half(p1));
            phg8[j] = pack_h(__float2half(p2), __float2half(p3));
        }
        ls0 += __shfl_xor_sync(0xffffffffu, ls0, 1);
        ls0 += __shfl_xor_sync(0xffffffffu, ls0, 2);
        ls8 += __shfl_xor_sync(0xffffffffu, ls8, 1);
        ls8 += __shfl_xor_sync(0xffffffffu, ls8, 2);
        l0 = l0 * f0 + ls0;
        l8 = l8 * f8 + ls8;
        m0 = mn0; m8 = mn8;

#pragma unroll
        for (int j = 0; j < 8; j++) {
            oacc[j][0] *= f0; oacc[j][1] *= f0;
            oacc[j][2] *= f8; oacc[j][3] *= f8;
        }

        // ---- O += P V (skip all-zero P key groups) ----
#pragma unroll
        for (int t = 0; t < 4; t++) {
            if (t < plo || t > phi) continue;    // warp-uniform skip
            uint32_t vh[8][2];
            int row = t * 16 + lr;               // key row for this lane
            uint32_t rbase = bV + (uint32_t)row * 128;
            uint32_t rsw = (uint32_t)(row & 7);
#pragma unroll
            for (int pp = 0; pp < 4; pp++) {
                uint32_t d = (uint32_t)(pp * 2) + (uint32_t)lh;  // dim group (16B)
                uint32_t addr = rbase + ((d ^ rsw) * 16);
                uint32_t r0, r1, r2, r3;
                ldm_x4_t(r0, r1, r2, r3, addr);
                vh[pp * 2][0] = r0;     vh[pp * 2][1] = r1;
                vh[pp * 2 + 1][0] = r2; vh[pp * 2 + 1][1] = r3;
            }
            uint32_t pa_h[4] = {phg[2 * t], phg8[2 * t], phg[2 * t + 1], phg8[2 * t + 1]};
#pragma unroll
            for (int j = 0; j < 8; j++)
                mma_f16(oacc[j], pa_h, vh[j]);
        }
    }

    // ---- epilogue: normalize, store plain fp16 ----
    float il0 = 1.f / l0, il8 = 1.f / l8;
    size_t r0base = (tok0 + qg0) * EMB + colh;
    size_t r8base = (tok0 + qg8) * EMB + colh;
#pragma unroll
    for (int j = 0; j < 8; j++) {
        int col = j * 8 + tg * 2;
        *(uint32_t*)&g_oh[r0base + col] =
            pack_h(__float2half(oacc[j][0] * il0), __float2half(oacc[j][1] * il0));
        *(uint32_t*)&g_oh[r8base + col] =
            pack_h(__float2half(oacc[j][2] * il8), __float2half(oacc[j][3] * il8));
    }
}

// ---------------------------------------------------------------------------
extern "C" void kernel_launch(void* const* d_in, const int* in_sizes, int n_in,
                              void* d_out, int out_size)
{
    const float* x  = (const float*)d_in[0];
    const float* Wq = (const float*)d_in[1];
    const float* bq = (const float*)d_in[2];
    const float* Wk = (const float*)d_in[3];
    const float* bk = (const float*)d_in[4];
    const float* Wv = (const float*)d_in[5];
    const float* bv = (const float*)d_in[6];
    const float* Wo = (const float*)d_in[7];
    const float* bo = (const float*)d_in[8];
    float* out = (float*)d_out;

    cudaFuncSetAttribute(gemm_mma, cudaFuncAttributeMaxDynamicSharedMemorySize, GEMM_SMEM);

    int n4 = MTOT * EMB / 4;
    int w4 = EMB * EMB / 4;
    conv_x<<<(n4 + 255) / 256, 256>>>(x, n4);
    conv_w<<<dim3((w4 + 255) / 256, 4), 256>>>(Wq, Wk, Wv, Wo, w4);

    gemm_mma<<<dim3(MTOT / 128, EMB / 128, 3), 256, GEMM_SMEM>>>(bq, bk, bv, nullptr, 0);

    attn_mma<<<dim3(SEQ / 64, NHEAD, BATCH), 128>>>();

    gemm_mma<<<dim3(MTOT / 128, EMB / 128, 1), 256, GEMM_SMEM>>>(bo, nullptr, nullptr, out, 1);
}